// round 12
// baseline (speedup 1.0000x reference)
#include <cuda_runtime.h>
#include <cstdint>

#define N_NODES 50000
#define N_EDGES 800000
#define D_IN    128
#define D_HID   128
#define D_MLP   256
#define D_OUT   10

// ---------------- scratch (static device globals: no allocations) ----------
__device__ float g_dis[N_NODES];             // deg^{-1/2}
__device__ int   g_cnt[N_NODES];             // in-degree counts (no self-loop)
__device__ int   g_cur[N_NODES];             // fill cursors (init = rowoff)
__device__ int   g_rowoff[N_NODES + 1];      // CSR row offsets (by dst)
__device__ int   g_csrc[N_EDGES];            // CSR src indices
__device__ float g_t [N_NODES * D_HID];      // t = h @ W (pre-aggregation)
__device__ float g_h [N_NODES * D_HID];      // aggregated hidden
__device__ float g_h2[N_NODES * D_MLP];      // MLP hidden

// ---------------- CSR build ----------------
__global__ void k_zero(int* __restrict__ cnt) {
    int i = blockIdx.x * blockDim.x + threadIdx.x;
    if (i < N_NODES) cnt[i] = 0;
}

__global__ void k_count(const int* __restrict__ ei, int* __restrict__ cnt) {
    int e = blockIdx.x * blockDim.x + threadIdx.x;
    if (e < N_EDGES) atomicAdd(&cnt[ei[N_EDGES + e]], 1);
}

// exclusive scan; writes rowoff AND cur (cursor copy); dis = rsqrt(deg)
__global__ void __launch_bounds__(1024) k_scan(
    const int* __restrict__ cnt, int* __restrict__ rowoff,
    int* __restrict__ cur, float* __restrict__ dis)
{
    __shared__ int part[1024];
    const int PER = (N_NODES + 1023) / 1024;    // 49
    int t = threadIdx.x;
    int base = t * PER;

    int sum = 0;
    for (int i = 0; i < PER; i++) {
        int idx = base + i;
        if (idx < N_NODES) sum += cnt[idx];
    }
    part[t] = sum;
    __syncthreads();
    for (int off = 1; off < 1024; off <<= 1) {
        int v = (t >= off) ? part[t - off] : 0;
        __syncthreads();
        part[t] += v;
        __syncthreads();
    }
    int running = (t == 0) ? 0 : part[t - 1];
    for (int i = 0; i < PER; i++) {
        int idx = base + i;
        if (idx < N_NODES) {
            int c = cnt[idx];
            rowoff[idx] = running;
            cur[idx]    = running;
            running += c;
            dis[idx] = rsqrtf((float)(c + 1));
        }
    }
    if (t == 1023) rowoff[N_NODES] = part[1023];
}

__global__ void k_fill(const int* __restrict__ ei,
                       int* __restrict__ cur, int* __restrict__ csrc)
{
    int e = blockIdx.x * blockDim.x + threadIdx.x;
    if (e < N_EDGES) {
        int s = ei[e];
        int d = ei[N_EDGES + e];
        csrc[atomicAdd(&cur[d], 1)] = s;
    }
}

// ---------------- TF32 tensor-core GEMM (mma.sync) ---------------------------
// C[M,Ncols] = op(A[M,K]) @ B[K,Ncols] (+bias)(+relu)
__device__ __forceinline__ uint32_t f2tf32(float f) {
    uint32_t r;
    asm("cvt.rna.tf32.f32 %0, %1;" : "=r"(r) : "f"(f));
    return r;
}

template<bool RELU_A, bool BIAS, bool RELU_OUT>
__global__ void __launch_bounds__(256, 2) k_gemm_tc(
    const float* __restrict__ A, const float* __restrict__ B,
    const float* __restrict__ bias, float* __restrict__ C,
    int M, int Ncols, int K)
{
    __shared__ uint32_t As[128][36];
    __shared__ uint32_t Bs[32][132];

    const int tid    = threadIdx.x;
    const int lane   = tid & 31;
    const int wid    = tid >> 5;
    const int warp_m = wid & 3;
    const int warp_n = wid >> 2;
    const int row0   = blockIdx.x * 128;
    const int col0   = blockIdx.y * 128;

    const int g  = lane >> 2;
    const int tg = lane & 3;

    float c[2][8][4];
#pragma unroll
    for (int mf = 0; mf < 2; mf++)
#pragma unroll
        for (int nf = 0; nf < 8; nf++)
#pragma unroll
            for (int i = 0; i < 4; i++) c[mf][nf][i] = 0.0f;

    const int a_r  = tid >> 3;
    const int a_c4 = (tid & 7) * 4;
    const int b_k  = tid >> 5;
    const int b_c4 = lane * 4;

    float4 pa[4], pb[4];

#pragma unroll
    for (int i = 0; i < 4; i++) {
        int r = a_r + i * 32;
        pa[i] = make_float4(0.f, 0.f, 0.f, 0.f);
        if (row0 + r < M)
            pa[i] = *(const float4*)(A + (size_t)(row0 + r) * K + a_c4);
    }
#pragma unroll
    for (int j = 0; j < 4; j++)
        pb[j] = *(const float4*)(B + (size_t)(b_k + j * 8) * Ncols + col0 + b_c4);

    const int NIT = K / 32;
    for (int it = 0; it < NIT; it++) {
#pragma unroll
        for (int i = 0; i < 4; i++) {
            int r = a_r + i * 32;
            float4 v = pa[i];
            if (RELU_A) {
                v.x = fmaxf(v.x, 0.f); v.y = fmaxf(v.y, 0.f);
                v.z = fmaxf(v.z, 0.f); v.w = fmaxf(v.w, 0.f);
            }
            As[r][a_c4 + 0] = f2tf32(v.x); As[r][a_c4 + 1] = f2tf32(v.y);
            As[r][a_c4 + 2] = f2tf32(v.z); As[r][a_c4 + 3] = f2tf32(v.w);
        }
#pragma unroll
        for (int j = 0; j < 4; j++) {
            int k = b_k + j * 8;
            float4 v = pb[j];
            Bs[k][b_c4 + 0] = f2tf32(v.x); Bs[k][b_c4 + 1] = f2tf32(v.y);
            Bs[k][b_c4 + 2] = f2tf32(v.z); Bs[k][b_c4 + 3] = f2tf32(v.w);
        }
        __syncthreads();

        if (it + 1 < NIT) {
            int k0 = (it + 1) * 32;
#pragma unroll
            for (int i = 0; i < 4; i++) {
                int r = a_r + i * 32;
                pa[i] = make_float4(0.f, 0.f, 0.f, 0.f);
                if (row0 + r < M)
                    pa[i] = *(const float4*)(A + (size_t)(row0 + r) * K + k0 + a_c4);
            }
#pragma unroll
            for (int j = 0; j < 4; j++)
                pb[j] = *(const float4*)(B + (size_t)(k0 + b_k + j * 8) * Ncols + col0 + b_c4);
        }

#pragma unroll
        for (int kk = 0; kk < 4; kk++) {
            const int kb = kk * 8;
            uint32_t af[2][4];
#pragma unroll
            for (int mf = 0; mf < 2; mf++) {
                int rs = warp_m * 32 + mf * 16 + g;
                af[mf][0] = As[rs    ][kb + tg    ];
                af[mf][1] = As[rs + 8][kb + tg    ];
                af[mf][2] = As[rs    ][kb + tg + 4];
                af[mf][3] = As[rs + 8][kb + tg + 4];
            }
            uint32_t bf[8][2];
#pragma unroll
            for (int nf = 0; nf < 8; nf++) {
                int ns = warp_n * 64 + nf * 8 + g;
                bf[nf][0] = Bs[kb + tg    ][ns];
                bf[nf][1] = Bs[kb + tg + 4][ns];
            }
#pragma unroll
            for (int mf = 0; mf < 2; mf++)
#pragma unroll
                for (int nf = 0; nf < 8; nf++) {
                    asm volatile(
                        "mma.sync.aligned.m16n8k8.row.col.f32.tf32.tf32.f32 "
                        "{%0,%1,%2,%3}, {%4,%5,%6,%7}, {%8,%9}, {%0,%1,%2,%3};"
                        : "+f"(c[mf][nf][0]), "+f"(c[mf][nf][1]),
                          "+f"(c[mf][nf][2]), "+f"(c[mf][nf][3])
                        : "r"(af[mf][0]), "r"(af[mf][1]), "r"(af[mf][2]), "r"(af[mf][3]),
                          "r"(bf[nf][0]), "r"(bf[nf][1]));
                }
        }
        __syncthreads();
    }

#pragma unroll
    for (int mf = 0; mf < 2; mf++) {
        int rbase = row0 + warp_m * 32 + mf * 16 + g;
#pragma unroll
        for (int nf = 0; nf < 8; nf++) {
            int col = col0 + warp_n * 64 + nf * 8 + tg * 2;
            float b0 = 0.f, b1 = 0.f;
            if (BIAS) { b0 = bias[col]; b1 = bias[col + 1]; }
#pragma unroll
            for (int half = 0; half < 2; half++) {
                int r = rbase + half * 8;
                if (r < M) {
                    float v0 = c[mf][nf][half * 2 + 0] + b0;
                    float v1 = c[mf][nf][half * 2 + 1] + b1;
                    if (RELU_OUT) { v0 = fmaxf(v0, 0.f); v1 = fmaxf(v1, 0.f); }
                    float2 o = make_float2(v0, v1);
                    *(float2*)(C + (size_t)r * Ncols + col) = o;
                }
            }
        }
    }
}

// ---------------- CSR gather aggregation (TWO warps per dst node) -----------
// global warp gw: node = gw>>1, half = gw&1; each warp covers 64 features
// (float2 per lane, 256B/warp/edge, fully coalesced). 2x warp-level
// parallelism vs one-warp-per-node to hide L2 latency.
__global__ void __launch_bounds__(256) k_gather(
    const int* __restrict__ csrc, const int* __restrict__ rowoff,
    const float* __restrict__ dis, const float* __restrict__ t,
    const float* __restrict__ bias, float* __restrict__ h)
{
    int gw   = (blockIdx.x * 256 + threadIdx.x) >> 5;
    int lane = threadIdx.x & 31;
    int w    = gw >> 1;
    int half = gw & 1;
    if (w >= N_NODES) return;

    int beg = rowoff[w], end = rowoff[w + 1];
    float dd = dis[w];

    const int fo = half * 64 + lane * 2;   // feature offset for this lane

    float2 acc = make_float2(0.f, 0.f);
    for (int eb = beg; eb < end; eb += 32) {
        int n = end - eb; if (n > 32) n = 32;
        int   s_l  = (lane < n) ? __ldg(csrc + eb + lane) : 0;
        float ns_l = (lane < n) ? __ldg(dis + s_l) : 0.f;
#pragma unroll 4
        for (int j = 0; j < n; j++) {
            int   s  = __shfl_sync(0xffffffffu, s_l,  j);
            float ns = __shfl_sync(0xffffffffu, ns_l, j);
            float2 v = *(const float2*)(t + (size_t)s * D_HID + fo);
            acc.x = fmaf(ns, v.x, acc.x);
            acc.y = fmaf(ns, v.y, acc.y);
        }
    }

    float2 tv = *(const float2*)(t + (size_t)w * D_HID + fo);
    float2 bv = ((const float2*)bias)[half * 32 + lane];
    float dd2 = dd * dd;
    float2 o;
    o.x = fmaf(dd, acc.x, fmaf(dd2, tv.x, bv.x));
    o.y = fmaf(dd, acc.y, fmaf(dd2, tv.y, bv.y));
    *(float2*)(h + (size_t)w * D_HID + fo) = o;
}

// ---------------- final: out[M,10] = H[M,256] @ W[256,10] + b ---------------
__global__ void __launch_bounds__(256) k_final(
    const float* __restrict__ H, const float* __restrict__ W,
    const float* __restrict__ b, float* __restrict__ out, int M)
{
    __shared__ float sW[D_MLP * D_OUT];
    __shared__ float sb[D_OUT];
    for (int k = threadIdx.x; k < D_MLP * D_OUT; k += 256) sW[k] = W[k];
    if (threadIdx.x < D_OUT) sb[threadIdx.x] = b[threadIdx.x];
    __syncthreads();

    int w    = (blockIdx.x * 256 + threadIdx.x) >> 5;
    int lane = threadIdx.x & 31;
    if (w >= M) return;

    const float* hrow = H + (size_t)w * D_MLP;
    float acc[D_OUT];
#pragma unroll
    for (int j = 0; j < D_OUT; j++) acc[j] = 0.0f;

#pragma unroll
    for (int kk = 0; kk < D_MLP / 32; kk++) {
        int k = kk * 32 + lane;
        float hv = hrow[k];
        const float* wr = &sW[k * D_OUT];
#pragma unroll
        for (int j = 0; j < D_OUT; j++) acc[j] = fmaf(hv, wr[j], acc[j]);
    }
#pragma unroll
    for (int j = 0; j < D_OUT; j++) {
#pragma unroll
        for (int off = 16; off; off >>= 1)
            acc[j] += __shfl_down_sync(0xffffffffu, acc[j], off);
    }
    if (lane == 0) {
#pragma unroll
        for (int j = 0; j < D_OUT; j++)
            out[(size_t)w * D_OUT + j] = acc[j] + sb[j];
    }
}

// ---------------------------------------------------------------------------
extern "C" void kernel_launch(void* const* d_in, const int* in_sizes, int n_in,
                              void* d_out, int out_size)
{
    const float* x   = (const float*)d_in[0];
    const int*   ei  = (const int*)d_in[1];     // int32 (JAX x64 disabled)
    const float* W0  = (const float*)d_in[2];
    const float* b0  = (const float*)d_in[3];
    const float* W1  = (const float*)d_in[4];
    const float* b1  = (const float*)d_in[5];
    const float* Wm1 = (const float*)d_in[6];
    const float* bm1 = (const float*)d_in[7];
    const float* Wm2 = (const float*)d_in[8];
    const float* bm2 = (const float*)d_in[9];
    float* out = (float*)d_out;

    float *dis, *t, *h, *h2;
    int *cnt, *cur, *rowoff, *csrc;
    cudaGetSymbolAddress((void**)&dis, g_dis);
    cudaGetSymbolAddress((void**)&t,   g_t);
    cudaGetSymbolAddress((void**)&h,   g_h);
    cudaGetSymbolAddress((void**)&h2,  g_h2);
    cudaGetSymbolAddress((void**)&cnt, g_cnt);
    cudaGetSymbolAddress((void**)&cur, g_cur);
    cudaGetSymbolAddress((void**)&rowoff, g_rowoff);
    cudaGetSymbolAddress((void**)&csrc, g_csrc);

    const int ngrid = (N_NODES + 255) / 256;
    const int egrid = (N_EDGES + 255) / 256;
    const dim3 gemm_grid1((N_NODES + 127) / 128, 1);
    const dim3 gemm_grid2((N_NODES + 127) / 128, 2);
    const int  gather_grid = (N_NODES * 64 + 255) / 256;   // 2 warps per node

    // ---- CSR build ----
    k_zero <<<ngrid, 256>>>(cnt);
    k_count<<<egrid, 256>>>(ei, cnt);
    k_scan <<<1, 1024>>>(cnt, rowoff, cur, dis);
    k_fill <<<egrid, 256>>>(ei, cur, csrc);

    // layer 0
    k_gemm_tc<false, false, false><<<gemm_grid1, 256>>>(x, W0, nullptr, t, N_NODES, D_HID, D_IN);
    k_gather<<<gather_grid, 256>>>(csrc, rowoff, dis, t, b0, h);

    // layer 1 (relu fused into GEMM A-load)
    k_gemm_tc<true, false, false><<<gemm_grid1, 256>>>(h, W1, nullptr, t, N_NODES, D_HID, D_HID);
    k_gather<<<gather_grid, 256>>>(csrc, rowoff, dis, t, b1, h);

    // MLP head (R4 proven shape)
    k_gemm_tc<false, true, true><<<gemm_grid2, 256>>>(h, Wm1, bm1, h2, N_NODES, D_MLP, D_HID);
    k_final<<<(N_NODES * 32 + 255) / 256, 256>>>(h2, Wm2, bm2, out, N_NODES);
}

// round 13
// speedup vs baseline: 1.4810x; 1.4810x over previous
#include <cuda_runtime.h>
#include <cstdint>

#define N_NODES 50000
#define N_EDGES 800000
#define D_IN    128
#define D_HID   128
#define D_MLP   256
#define D_OUT   10

#define SCAN_BLKS ((N_NODES + 1023) / 1024)   // 49

// ---------------- scratch (static device globals: no allocations) ----------
__device__ float g_dis[N_NODES];             // deg^{-1/2}
__device__ int   g_cnt[N_NODES];             // in-degree counts (no self-loop)
__device__ int   g_cur[N_NODES];             // fill cursors
__device__ int   g_rowoff[N_NODES + 1];      // CSR row offsets (by dst)
__device__ int   g_loc[N_NODES];             // block-local exclusive scan
__device__ int   g_bsum[SCAN_BLKS];          // per-block sums
__device__ int   g_boff[SCAN_BLKS + 1];      // scanned block offsets
__device__ int   g_csrc[N_EDGES];            // CSR src indices
__device__ float g_t [N_NODES * D_HID];      // t = h @ W (pre-aggregation)
__device__ float g_h [N_NODES * D_HID];      // aggregated hidden
__device__ float g_h2[N_NODES * D_MLP];      // MLP hidden

// ---------------- CSR build ----------------
__global__ void k_zero(int* __restrict__ cnt, int* __restrict__ cur) {
    int i = blockIdx.x * blockDim.x + threadIdx.x;
    if (i < N_NODES) { cnt[i] = 0; cur[i] = 0; }
}

__global__ void k_count(const int* __restrict__ ei, int* __restrict__ cnt) {
    int e = blockIdx.x * blockDim.x + threadIdx.x;
    if (e < N_EDGES) atomicAdd(&cnt[ei[N_EDGES + e]], 1);
}

// --- hierarchical coalesced scan (replaces single-block strided k_scan) ---
__global__ void __launch_bounds__(1024) k_scanA(
    const int* __restrict__ cnt, int* __restrict__ loc, int* __restrict__ bsum)
{
    __shared__ int sh[1024];
    int b = blockIdx.x, t = threadIdx.x;
    int idx = b * 1024 + t;
    int v = (idx < N_NODES) ? cnt[idx] : 0;
    sh[t] = v;
    __syncthreads();
    for (int off = 1; off < 1024; off <<= 1) {
        int u = (t >= off) ? sh[t - off] : 0;
        __syncthreads();
        sh[t] += u;
        __syncthreads();
    }
    if (idx < N_NODES) loc[idx] = sh[t] - v;     // exclusive
    if (t == 1023) bsum[b] = sh[1023];
}

__global__ void __launch_bounds__(64) k_scanB(
    const int* __restrict__ bsum, int* __restrict__ boff)
{
    __shared__ int sh[64];
    int t = threadIdx.x;
    int v = (t < SCAN_BLKS) ? bsum[t] : 0;
    sh[t] = v;
    __syncthreads();
    for (int off = 1; off < 64; off <<= 1) {
        int u = (t >= off) ? sh[t - off] : 0;
        __syncthreads();
        sh[t] += u;
        __syncthreads();
    }
    if (t < SCAN_BLKS) boff[t] = sh[t] - v;      // exclusive
    if (t == SCAN_BLKS - 1) boff[SCAN_BLKS] = sh[t];
}

__global__ void __launch_bounds__(1024) k_scanC(
    const int* __restrict__ cnt, const int* __restrict__ loc,
    const int* __restrict__ boff, int* __restrict__ rowoff,
    float* __restrict__ dis)
{
    int b = blockIdx.x, t = threadIdx.x;
    int idx = b * 1024 + t;
    if (idx < N_NODES) {
        rowoff[idx] = loc[idx] + boff[b];
        dis[idx] = rsqrtf((float)(cnt[idx] + 1));
    }
    if (idx == 0) rowoff[N_NODES] = boff[SCAN_BLKS];
}

__global__ void k_fill(const int* __restrict__ ei, const int* __restrict__ rowoff,
                       int* __restrict__ cur, int* __restrict__ csrc)
{
    int e = blockIdx.x * blockDim.x + threadIdx.x;
    if (e < N_EDGES) {
        int s = ei[e];
        int d = ei[N_EDGES + e];
        int pos = rowoff[d] + atomicAdd(&cur[d], 1);
        csrc[pos] = s;
    }
}

// ---------------- TF32 tensor-core GEMM (R4-exact) --------------------------
// C[M,Ncols] = op(A[M,K]) @ B[K,Ncols] (+bias)(+relu)
__device__ __forceinline__ uint32_t f2tf32(float f) {
    uint32_t r;
    asm("cvt.rna.tf32.f32 %0, %1;" : "=r"(r) : "f"(f));
    return r;
}

template<bool RELU_A, bool BIAS, bool RELU_OUT>
__global__ void __launch_bounds__(256, 2) k_gemm_tc(
    const float* __restrict__ A, const float* __restrict__ B,
    const float* __restrict__ bias, float* __restrict__ C,
    int M, int Ncols, int K)
{
    __shared__ float As[128][36];
    __shared__ float Bs[32][132];

    const int tid    = threadIdx.x;
    const int lane   = tid & 31;
    const int wid    = tid >> 5;
    const int warp_m = wid & 3;
    const int warp_n = wid >> 2;
    const int row0   = blockIdx.x * 128;
    const int col0   = blockIdx.y * 128;

    const int g  = lane >> 2;
    const int tg = lane & 3;

    float c[2][8][4];
#pragma unroll
    for (int mf = 0; mf < 2; mf++)
#pragma unroll
        for (int nf = 0; nf < 8; nf++)
#pragma unroll
            for (int i = 0; i < 4; i++) c[mf][nf][i] = 0.0f;

    const int a_r  = tid >> 3;
    const int a_c4 = (tid & 7) * 4;
    const int b_k  = tid >> 5;
    const int b_c4 = lane * 4;

    for (int k0 = 0; k0 < K; k0 += 32) {
#pragma unroll
        for (int i = 0; i < 4; i++) {
            int r = a_r + i * 32;
            float4 v = make_float4(0.f, 0.f, 0.f, 0.f);
            if (row0 + r < M)
                v = *(const float4*)(A + (size_t)(row0 + r) * K + k0 + a_c4);
            if (RELU_A) {
                v.x = fmaxf(v.x, 0.f); v.y = fmaxf(v.y, 0.f);
                v.z = fmaxf(v.z, 0.f); v.w = fmaxf(v.w, 0.f);
            }
            *(float4*)&As[r][a_c4] = v;
        }
#pragma unroll
        for (int j = 0; j < 4; j++) {
            int k = b_k + j * 8;
            float4 v = *(const float4*)(B + (size_t)(k0 + k) * Ncols + col0 + b_c4);
            *(float4*)&Bs[k][b_c4] = v;
        }
        __syncthreads();

#pragma unroll
        for (int kk = 0; kk < 4; kk++) {
            const int kb = kk * 8;
            uint32_t af[2][4];
#pragma unroll
            for (int mf = 0; mf < 2; mf++) {
                int rs = warp_m * 32 + mf * 16 + g;
                af[mf][0] = f2tf32(As[rs    ][kb + tg    ]);
                af[mf][1] = f2tf32(As[rs + 8][kb + tg    ]);
                af[mf][2] = f2tf32(As[rs    ][kb + tg + 4]);
                af[mf][3] = f2tf32(As[rs + 8][kb + tg + 4]);
            }
            uint32_t bf[8][2];
#pragma unroll
            for (int nf = 0; nf < 8; nf++) {
                int ns = warp_n * 64 + nf * 8 + g;
                bf[nf][0] = f2tf32(Bs[kb + tg    ][ns]);
                bf[nf][1] = f2tf32(Bs[kb + tg + 4][ns]);
            }
#pragma unroll
            for (int mf = 0; mf < 2; mf++)
#pragma unroll
                for (int nf = 0; nf < 8; nf++) {
                    asm volatile(
                        "mma.sync.aligned.m16n8k8.row.col.f32.tf32.tf32.f32 "
                        "{%0,%1,%2,%3}, {%4,%5,%6,%7}, {%8,%9}, {%0,%1,%2,%3};"
                        : "+f"(c[mf][nf][0]), "+f"(c[mf][nf][1]),
                          "+f"(c[mf][nf][2]), "+f"(c[mf][nf][3])
                        : "r"(af[mf][0]), "r"(af[mf][1]), "r"(af[mf][2]), "r"(af[mf][3]),
                          "r"(bf[nf][0]), "r"(bf[nf][1]));
                }
        }
        __syncthreads();
    }

#pragma unroll
    for (int mf = 0; mf < 2; mf++) {
        int rbase = row0 + warp_m * 32 + mf * 16 + g;
#pragma unroll
        for (int nf = 0; nf < 8; nf++) {
            int col = col0 + warp_n * 64 + nf * 8 + tg * 2;
            float b0 = 0.f, b1 = 0.f;
            if (BIAS) { b0 = bias[col]; b1 = bias[col + 1]; }
#pragma unroll
            for (int half = 0; half < 2; half++) {
                int r = rbase + half * 8;
                if (r < M) {
                    float v0 = c[mf][nf][half * 2 + 0] + b0;
                    float v1 = c[mf][nf][half * 2 + 1] + b1;
                    if (RELU_OUT) { v0 = fmaxf(v0, 0.f); v1 = fmaxf(v1, 0.f); }
                    float2 o = make_float2(v0, v1);
                    *(float2*)(C + (size_t)r * Ncols + col) = o;
                }
            }
        }
    }
}

// ---------------- CSR gather aggregation (R4-exact) --------------------------
__global__ void __launch_bounds__(256) k_gather(
    const int* __restrict__ csrc, const int* __restrict__ rowoff,
    const float* __restrict__ dis, const float* __restrict__ t,
    const float* __restrict__ bias, float* __restrict__ h)
{
    int w    = (blockIdx.x * 256 + threadIdx.x) >> 5;
    int lane = threadIdx.x & 31;
    if (w >= N_NODES) return;

    int beg = rowoff[w], end = rowoff[w + 1];
    float dd = dis[w];

    float4 acc = make_float4(0.f, 0.f, 0.f, 0.f);
    for (int eb = beg; eb < end; eb += 32) {
        int n = end - eb; if (n > 32) n = 32;
        int   s_l  = (lane < n) ? __ldg(csrc + eb + lane) : 0;
        float ns_l = (lane < n) ? __ldg(dis + s_l) : 0.f;
#pragma unroll 4
        for (int j = 0; j < n; j++) {
            int   s  = __shfl_sync(0xffffffffu, s_l,  j);
            float ns = __shfl_sync(0xffffffffu, ns_l, j);
            float4 v = *(const float4*)(t + (size_t)s * D_HID + lane * 4);
            acc.x = fmaf(ns, v.x, acc.x); acc.y = fmaf(ns, v.y, acc.y);
            acc.z = fmaf(ns, v.z, acc.z); acc.w = fmaf(ns, v.w, acc.w);
        }
    }

    float4 tv = *(const float4*)(t + (size_t)w * D_HID + lane * 4);
    float4 bv = ((const float4*)bias)[lane];
    float dd2 = dd * dd;
    float4 o;
    o.x = fmaf(dd, acc.x, fmaf(dd2, tv.x, bv.x));
    o.y = fmaf(dd, acc.y, fmaf(dd2, tv.y, bv.y));
    o.z = fmaf(dd, acc.z, fmaf(dd2, tv.z, bv.z));
    o.w = fmaf(dd, acc.w, fmaf(dd2, tv.w, bv.w));
    *(float4*)(h + (size_t)w * D_HID + lane * 4) = o;
}

// ---------------- final: out[M,10] = H[M,256] @ W[256,10] + b ---------------
__global__ void __launch_bounds__(256) k_final(
    const float* __restrict__ H, const float* __restrict__ W,
    const float* __restrict__ b, float* __restrict__ out, int M)
{
    __shared__ float sW[D_MLP * D_OUT];
    __shared__ float sb[D_OUT];
    for (int k = threadIdx.x; k < D_MLP * D_OUT; k += 256) sW[k] = W[k];
    if (threadIdx.x < D_OUT) sb[threadIdx.x] = b[threadIdx.x];
    __syncthreads();

    int w    = (blockIdx.x * 256 + threadIdx.x) >> 5;
    int lane = threadIdx.x & 31;
    if (w >= M) return;

    const float* hrow = H + (size_t)w * D_MLP;
    float acc[D_OUT];
#pragma unroll
    for (int j = 0; j < D_OUT; j++) acc[j] = 0.0f;

#pragma unroll
    for (int kk = 0; kk < D_MLP / 32; kk++) {
        int k = kk * 32 + lane;
        float hv = hrow[k];
        const float* wr = &sW[k * D_OUT];
#pragma unroll
        for (int j = 0; j < D_OUT; j++) acc[j] = fmaf(hv, wr[j], acc[j]);
    }
#pragma unroll
    for (int j = 0; j < D_OUT; j++) {
#pragma unroll
        for (int off = 16; off; off >>= 1)
            acc[j] += __shfl_down_sync(0xffffffffu, acc[j], off);
    }
    if (lane == 0) {
#pragma unroll
        for (int j = 0; j < D_OUT; j++)
            out[(size_t)w * D_OUT + j] = acc[j] + sb[j];
    }
}

// ---------------------------------------------------------------------------
extern "C" void kernel_launch(void* const* d_in, const int* in_sizes, int n_in,
                              void* d_out, int out_size)
{
    const float* x   = (const float*)d_in[0];
    const int*   ei  = (const int*)d_in[1];     // int32 (JAX x64 disabled)
    const float* W0  = (const float*)d_in[2];
    const float* b0  = (const float*)d_in[3];
    const float* W1  = (const float*)d_in[4];
    const float* b1  = (const float*)d_in[5];
    const float* Wm1 = (const float*)d_in[6];
    const float* bm1 = (const float*)d_in[7];
    const float* Wm2 = (const float*)d_in[8];
    const float* bm2 = (const float*)d_in[9];
    float* out = (float*)d_out;

    float *dis, *t, *h, *h2;
    int *cnt, *cur, *rowoff, *csrc, *loc, *bsum, *boff;
    cudaGetSymbolAddress((void**)&dis, g_dis);
    cudaGetSymbolAddress((void**)&t,   g_t);
    cudaGetSymbolAddress((void**)&h,   g_h);
    cudaGetSymbolAddress((void**)&h2,  g_h2);
    cudaGetSymbolAddress((void**)&cnt, g_cnt);
    cudaGetSymbolAddress((void**)&cur, g_cur);
    cudaGetSymbolAddress((void**)&rowoff, g_rowoff);
    cudaGetSymbolAddress((void**)&csrc, g_csrc);
    cudaGetSymbolAddress((void**)&loc,  g_loc);
    cudaGetSymbolAddress((void**)&bsum, g_bsum);
    cudaGetSymbolAddress((void**)&boff, g_boff);

    const int ngrid = (N_NODES + 255) / 256;
    const int egrid = (N_EDGES + 255) / 256;

    // ---- CSR build (by dst) + norms; coalesced hierarchical scan ----
    k_zero <<<ngrid, 256>>>(cnt, cur);
    k_count<<<egrid, 256>>>(ei, cnt);
    k_scanA<<<SCAN_BLKS, 1024>>>(cnt, loc, bsum);
    k_scanB<<<1, 64>>>(bsum, boff);
    k_scanC<<<SCAN_BLKS, 1024>>>(cnt, loc, boff, rowoff, dis);
    k_fill <<<egrid, 256>>>(ei, rowoff, cur, csrc);

    const dim3 gemm_grid1((N_NODES + 127) / 128, 1);
    const dim3 gemm_grid2((N_NODES + 127) / 128, 2);
    const int  gather_grid = (N_NODES * 32 + 255) / 256;

    // layer 0
    k_gemm_tc<false, false, false><<<gemm_grid1, 256>>>(x, W0, nullptr, t, N_NODES, D_HID, D_IN);
    k_gather<<<gather_grid, 256>>>(csrc, rowoff, dis, t, b0, h);

    // layer 1 (relu fused into GEMM A-load)
    k_gemm_tc<true, false, false><<<gemm_grid1, 256>>>(h, W1, nullptr, t, N_NODES, D_HID, D_HID);
    k_gather<<<gather_grid, 256>>>(csrc, rowoff, dis, t, b1, h);

    // MLP head
    k_gemm_tc<false, true, true><<<gemm_grid2, 256>>>(h, Wm1, bm1, h2, N_NODES, D_MLP, D_HID);
    k_final<<<(N_NODES * 32 + 255) / 256, 256>>>(h2, Wm2, bm2, out, N_NODES);
}

// round 14
// speedup vs baseline: 1.5494x; 1.0461x over previous
#include <cuda_runtime.h>
#include <cstdint>

#define N_NODES 50000
#define N_EDGES 800000
#define D_IN    128
#define D_HID   128
#define D_MLP   256
#define D_OUT   10

#define SCAN_BLKS ((N_NODES + 1023) / 1024)   // 49

// ---------------- scratch (static device globals: no allocations) ----------
__device__ float g_dis[N_NODES];             // deg^{-1/2}
__device__ int   g_cnt[N_NODES];             // in-degree counts (no self-loop)
__device__ int   g_cur[N_NODES];             // fill cursors
__device__ int   g_rowoff[N_NODES + 1];      // CSR row offsets (by dst)
__device__ int   g_loc[N_NODES];             // block-local exclusive scan
__device__ int   g_bsum[SCAN_BLKS];          // per-block sums
__device__ int   g_boff[SCAN_BLKS + 1];      // scanned block offsets
__device__ int   g_csrc[N_EDGES];            // CSR src indices
__device__ float g_t [N_NODES * D_HID];      // t = h @ W (pre-aggregation)
__device__ float g_h [N_NODES * D_HID];      // aggregated hidden
__device__ float g_h2[N_NODES * D_MLP];      // MLP hidden

// ---------------- CSR build ----------------
__global__ void k_zero(int* __restrict__ cnt, int* __restrict__ cur) {
    int i = blockIdx.x * blockDim.x + threadIdx.x;
    if (i < N_NODES) { cnt[i] = 0; cur[i] = 0; }
}

__global__ void k_count(const int* __restrict__ ei, int* __restrict__ cnt) {
    int e = blockIdx.x * blockDim.x + threadIdx.x;
    if (e < N_EDGES) atomicAdd(&cnt[ei[N_EDGES + e]], 1);
}

// --- hierarchical coalesced scan ---
__global__ void __launch_bounds__(1024) k_scanA(
    const int* __restrict__ cnt, int* __restrict__ loc, int* __restrict__ bsum)
{
    __shared__ int sh[1024];
    int b = blockIdx.x, t = threadIdx.x;
    int idx = b * 1024 + t;
    int v = (idx < N_NODES) ? cnt[idx] : 0;
    sh[t] = v;
    __syncthreads();
    for (int off = 1; off < 1024; off <<= 1) {
        int u = (t >= off) ? sh[t - off] : 0;
        __syncthreads();
        sh[t] += u;
        __syncthreads();
    }
    if (idx < N_NODES) loc[idx] = sh[t] - v;     // exclusive
    if (t == 1023) bsum[b] = sh[1023];
}

__global__ void __launch_bounds__(64) k_scanB(
    const int* __restrict__ bsum, int* __restrict__ boff)
{
    __shared__ int sh[64];
    int t = threadIdx.x;
    int v = (t < SCAN_BLKS) ? bsum[t] : 0;
    sh[t] = v;
    __syncthreads();
    for (int off = 1; off < 64; off <<= 1) {
        int u = (t >= off) ? sh[t - off] : 0;
        __syncthreads();
        sh[t] += u;
        __syncthreads();
    }
    if (t < SCAN_BLKS) boff[t] = sh[t] - v;      // exclusive
    if (t == SCAN_BLKS - 1) boff[SCAN_BLKS] = sh[t];
}

__global__ void __launch_bounds__(1024) k_scanC(
    const int* __restrict__ cnt, const int* __restrict__ loc,
    const int* __restrict__ boff, int* __restrict__ rowoff,
    float* __restrict__ dis)
{
    int b = blockIdx.x, t = threadIdx.x;
    int idx = b * 1024 + t;
    if (idx < N_NODES) {
        rowoff[idx] = loc[idx] + boff[b];
        dis[idx] = rsqrtf((float)(cnt[idx] + 1));
    }
    if (idx == 0) rowoff[N_NODES] = boff[SCAN_BLKS];
}

__global__ void k_fill(const int* __restrict__ ei, const int* __restrict__ rowoff,
                       int* __restrict__ cur, int* __restrict__ csrc)
{
    int e = blockIdx.x * blockDim.x + threadIdx.x;
    if (e < N_EDGES) {
        int s = ei[e];
        int d = ei[N_EDGES + e];
        int pos = rowoff[d] + atomicAdd(&cur[d], 1);
        csrc[pos] = s;
    }
}

// ---------------- TF32 tensor-core GEMM (R4/R13-exact) -----------------------
__device__ __forceinline__ uint32_t f2tf32(float f) {
    uint32_t r;
    asm("cvt.rna.tf32.f32 %0, %1;" : "=r"(r) : "f"(f));
    return r;
}

template<bool RELU_A, bool BIAS, bool RELU_OUT>
__global__ void __launch_bounds__(256, 2) k_gemm_tc(
    const float* __restrict__ A, const float* __restrict__ B,
    const float* __restrict__ bias, float* __restrict__ C,
    int M, int Ncols, int K)
{
    __shared__ float As[128][36];
    __shared__ float Bs[32][132];

    const int tid    = threadIdx.x;
    const int lane   = tid & 31;
    const int wid    = tid >> 5;
    const int warp_m = wid & 3;
    const int warp_n = wid >> 2;
    const int row0   = blockIdx.x * 128;
    const int col0   = blockIdx.y * 128;

    const int g  = lane >> 2;
    const int tg = lane & 3;

    float c[2][8][4];
#pragma unroll
    for (int mf = 0; mf < 2; mf++)
#pragma unroll
        for (int nf = 0; nf < 8; nf++)
#pragma unroll
            for (int i = 0; i < 4; i++) c[mf][nf][i] = 0.0f;

    const int a_r  = tid >> 3;
    const int a_c4 = (tid & 7) * 4;
    const int b_k  = tid >> 5;
    const int b_c4 = lane * 4;

    for (int k0 = 0; k0 < K; k0 += 32) {
#pragma unroll
        for (int i = 0; i < 4; i++) {
            int r = a_r + i * 32;
            float4 v = make_float4(0.f, 0.f, 0.f, 0.f);
            if (row0 + r < M)
                v = *(const float4*)(A + (size_t)(row0 + r) * K + k0 + a_c4);
            if (RELU_A) {
                v.x = fmaxf(v.x, 0.f); v.y = fmaxf(v.y, 0.f);
                v.z = fmaxf(v.z, 0.f); v.w = fmaxf(v.w, 0.f);
            }
            *(float4*)&As[r][a_c4] = v;
        }
#pragma unroll
        for (int j = 0; j < 4; j++) {
            int k = b_k + j * 8;
            float4 v = *(const float4*)(B + (size_t)(k0 + k) * Ncols + col0 + b_c4);
            *(float4*)&Bs[k][b_c4] = v;
        }
        __syncthreads();

#pragma unroll
        for (int kk = 0; kk < 4; kk++) {
            const int kb = kk * 8;
            uint32_t af[2][4];
#pragma unroll
            for (int mf = 0; mf < 2; mf++) {
                int rs = warp_m * 32 + mf * 16 + g;
                af[mf][0] = f2tf32(As[rs    ][kb + tg    ]);
                af[mf][1] = f2tf32(As[rs + 8][kb + tg    ]);
                af[mf][2] = f2tf32(As[rs    ][kb + tg + 4]);
                af[mf][3] = f2tf32(As[rs + 8][kb + tg + 4]);
            }
            uint32_t bf[8][2];
#pragma unroll
            for (int nf = 0; nf < 8; nf++) {
                int ns = warp_n * 64 + nf * 8 + g;
                bf[nf][0] = f2tf32(Bs[kb + tg    ][ns]);
                bf[nf][1] = f2tf32(Bs[kb + tg + 4][ns]);
            }
#pragma unroll
            for (int mf = 0; mf < 2; mf++)
#pragma unroll
                for (int nf = 0; nf < 8; nf++) {
                    asm volatile(
                        "mma.sync.aligned.m16n8k8.row.col.f32.tf32.tf32.f32 "
                        "{%0,%1,%2,%3}, {%4,%5,%6,%7}, {%8,%9}, {%0,%1,%2,%3};"
                        : "+f"(c[mf][nf][0]), "+f"(c[mf][nf][1]),
                          "+f"(c[mf][nf][2]), "+f"(c[mf][nf][3])
                        : "r"(af[mf][0]), "r"(af[mf][1]), "r"(af[mf][2]), "r"(af[mf][3]),
                          "r"(bf[nf][0]), "r"(bf[nf][1]));
                }
        }
        __syncthreads();
    }

#pragma unroll
    for (int mf = 0; mf < 2; mf++) {
        int rbase = row0 + warp_m * 32 + mf * 16 + g;
#pragma unroll
        for (int nf = 0; nf < 8; nf++) {
            int col = col0 + warp_n * 64 + nf * 8 + tg * 2;
            float b0 = 0.f, b1 = 0.f;
            if (BIAS) { b0 = bias[col]; b1 = bias[col + 1]; }
#pragma unroll
            for (int half = 0; half < 2; half++) {
                int r = rbase + half * 8;
                if (r < M) {
                    float v0 = c[mf][nf][half * 2 + 0] + b0;
                    float v1 = c[mf][nf][half * 2 + 1] + b1;
                    if (RELU_OUT) { v0 = fmaxf(v0, 0.f); v1 = fmaxf(v1, 0.f); }
                    float2 o = make_float2(v0, v1);
                    *(float2*)(C + (size_t)r * Ncols + col) = o;
                }
            }
        }
    }
}

// ---------------- CSR gather aggregation (R4-exact) --------------------------
__global__ void __launch_bounds__(256) k_gather(
    const int* __restrict__ csrc, const int* __restrict__ rowoff,
    const float* __restrict__ dis, const float* __restrict__ t,
    const float* __restrict__ bias, float* __restrict__ h)
{
    int w    = (blockIdx.x * 256 + threadIdx.x) >> 5;
    int lane = threadIdx.x & 31;
    if (w >= N_NODES) return;

    int beg = rowoff[w], end = rowoff[w + 1];
    float dd = dis[w];

    float4 acc = make_float4(0.f, 0.f, 0.f, 0.f);
    for (int eb = beg; eb < end; eb += 32) {
        int n = end - eb; if (n > 32) n = 32;
        int   s_l  = (lane < n) ? __ldg(csrc + eb + lane) : 0;
        float ns_l = (lane < n) ? __ldg(dis + s_l) : 0.f;
#pragma unroll 4
        for (int j = 0; j < n; j++) {
            int   s  = __shfl_sync(0xffffffffu, s_l,  j);
            float ns = __shfl_sync(0xffffffffu, ns_l, j);
            float4 v = *(const float4*)(t + (size_t)s * D_HID + lane * 4);
            acc.x = fmaf(ns, v.x, acc.x); acc.y = fmaf(ns, v.y, acc.y);
            acc.z = fmaf(ns, v.z, acc.z); acc.w = fmaf(ns, v.w, acc.w);
        }
    }

    float4 tv = *(const float4*)(t + (size_t)w * D_HID + lane * 4);
    float4 bv = ((const float4*)bias)[lane];
    float dd2 = dd * dd;
    float4 o;
    o.x = fmaf(dd, acc.x, fmaf(dd2, tv.x, bv.x));
    o.y = fmaf(dd, acc.y, fmaf(dd2, tv.y, bv.y));
    o.z = fmaf(dd, acc.z, fmaf(dd2, tv.z, bv.z));
    o.w = fmaf(dd, acc.w, fmaf(dd2, tv.w, bv.w));
    *(float4*)(h + (size_t)w * D_HID + lane * 4) = o;
}

// ---------------- final: out[M,10] = H[M,256] @ W[256,10] + b ---------------
__global__ void __launch_bounds__(256) k_final(
    const float* __restrict__ H, const float* __restrict__ W,
    const float* __restrict__ b, float* __restrict__ out, int M)
{
    __shared__ float sW[D_MLP * D_OUT];
    __shared__ float sb[D_OUT];
    for (int k = threadIdx.x; k < D_MLP * D_OUT; k += 256) sW[k] = W[k];
    if (threadIdx.x < D_OUT) sb[threadIdx.x] = b[threadIdx.x];
    __syncthreads();

    int w    = (blockIdx.x * 256 + threadIdx.x) >> 5;
    int lane = threadIdx.x & 31;
    if (w >= M) return;

    const float* hrow = H + (size_t)w * D_MLP;
    float acc[D_OUT];
#pragma unroll
    for (int j = 0; j < D_OUT; j++) acc[j] = 0.0f;

#pragma unroll
    for (int kk = 0; kk < D_MLP / 32; kk++) {
        int k = kk * 32 + lane;
        float hv = hrow[k];
        const float* wr = &sW[k * D_OUT];
#pragma unroll
        for (int j = 0; j < D_OUT; j++) acc[j] = fmaf(hv, wr[j], acc[j]);
    }
#pragma unroll
    for (int j = 0; j < D_OUT; j++) {
#pragma unroll
        for (int off = 16; off; off >>= 1)
            acc[j] += __shfl_down_sync(0xffffffffu, acc[j], off);
    }
    if (lane == 0) {
#pragma unroll
        for (int j = 0; j < D_OUT; j++)
            out[(size_t)w * D_OUT + j] = acc[j] + sb[j];
    }
}

// ---------------------------------------------------------------------------
extern "C" void kernel_launch(void* const* d_in, const int* in_sizes, int n_in,
                              void* d_out, int out_size)
{
    const float* x   = (const float*)d_in[0];
    const int*   ei  = (const int*)d_in[1];     // int32 (JAX x64 disabled)
    const float* W0  = (const float*)d_in[2];
    const float* b0  = (const float*)d_in[3];
    const float* W1  = (const float*)d_in[4];
    const float* b1  = (const float*)d_in[5];
    const float* Wm1 = (const float*)d_in[6];
    const float* bm1 = (const float*)d_in[7];
    const float* Wm2 = (const float*)d_in[8];
    const float* bm2 = (const float*)d_in[9];
    float* out = (float*)d_out;

    float *dis, *t, *h, *h2;
    int *cnt, *cur, *rowoff, *csrc, *loc, *bsum, *boff;
    cudaGetSymbolAddress((void**)&dis, g_dis);
    cudaGetSymbolAddress((void**)&t,   g_t);
    cudaGetSymbolAddress((void**)&h,   g_h);
    cudaGetSymbolAddress((void**)&h2,  g_h2);
    cudaGetSymbolAddress((void**)&cnt, g_cnt);
    cudaGetSymbolAddress((void**)&cur, g_cur);
    cudaGetSymbolAddress((void**)&rowoff, g_rowoff);
    cudaGetSymbolAddress((void**)&csrc, g_csrc);
    cudaGetSymbolAddress((void**)&loc,  g_loc);
    cudaGetSymbolAddress((void**)&bsum, g_bsum);
    cudaGetSymbolAddress((void**)&boff, g_boff);

    // side stream + events (host objects, created once on uncaptured call)
    static cudaStream_t s_csr = nullptr;
    static cudaEvent_t  ev_fork = nullptr, ev_csr = nullptr;
    if (s_csr == nullptr) {
        cudaStreamCreateWithFlags(&s_csr, cudaStreamNonBlocking);
        cudaEventCreateWithFlags(&ev_fork, cudaEventDisableTiming);
        cudaEventCreateWithFlags(&ev_csr,  cudaEventDisableTiming);
    }

    const int ngrid = (N_NODES + 255) / 256;
    const int egrid = (N_EDGES + 255) / 256;
    const dim3 gemm_grid1((N_NODES + 127) / 128, 1);
    const dim3 gemm_grid2((N_NODES + 127) / 128, 2);
    const int  gather_grid = (N_NODES * 32 + 255) / 256;

    // ---- fork: CSR chain on side stream, GEMM-0 on main stream ----
    cudaEventRecord(ev_fork, 0);
    cudaStreamWaitEvent(s_csr, ev_fork, 0);

    k_zero <<<ngrid, 256, 0, s_csr>>>(cnt, cur);
    k_count<<<egrid, 256, 0, s_csr>>>(ei, cnt);
    k_scanA<<<SCAN_BLKS, 1024, 0, s_csr>>>(cnt, loc, bsum);
    k_scanB<<<1, 64, 0, s_csr>>>(bsum, boff);
    k_scanC<<<SCAN_BLKS, 1024, 0, s_csr>>>(cnt, loc, boff, rowoff, dis);
    k_fill <<<egrid, 256, 0, s_csr>>>(ei, rowoff, cur, csrc);
    cudaEventRecord(ev_csr, s_csr);

    k_gemm_tc<false, false, false><<<gemm_grid1, 256>>>(x, W0, nullptr, t, N_NODES, D_HID, D_IN);

    // ---- join: gather needs both CSR and t ----
    cudaStreamWaitEvent(0, ev_csr, 0);
    k_gather<<<gather_grid, 256>>>(csrc, rowoff, dis, t, b0, h);

    // layer 1 (relu fused into GEMM A-load)
    k_gemm_tc<true, false, false><<<gemm_grid1, 256>>>(h, W1, nullptr, t, N_NODES, D_HID, D_HID);
    k_gather<<<gather_grid, 256>>>(csrc, rowoff, dis, t, b1, h);

    // MLP head
    k_gemm_tc<false, true, true><<<gemm_grid2, 256>>>(h, Wm1, bm1, h2, N_NODES, D_MLP, D_HID);
    k_final<<<(N_NODES * 32 + 255) / 256, 256>>>(h2, Wm2, bm2, out, N_NODES);
}

// round 15
// speedup vs baseline: 1.7418x; 1.1242x over previous
#include <cuda_runtime.h>
#include <cuda_fp16.h>
#include <cstdint>

#define N_NODES 50000
#define N_EDGES 800000
#define D_IN    128
#define D_HID   128
#define D_MLP   256
#define D_OUT   10

#define SCAN_BLKS ((N_NODES + 1023) / 1024)   // 49

// ---------------- scratch (static device globals: no allocations) ----------
__device__ float g_dis[N_NODES];             // deg^{-1/2}
__device__ int   g_cnt[N_NODES];             // in-degree counts (no self-loop)
__device__ int   g_cur[N_NODES];             // fill cursors
__device__ int   g_rowoff[N_NODES + 1];      // CSR row offsets (by dst)
__device__ int   g_loc[N_NODES];             // block-local exclusive scan
__device__ int   g_bsum[SCAN_BLKS];          // per-block sums
__device__ float g_t [N_NODES * D_HID];      // t = h @ W (pre-aggregation)
__device__ float g_h [N_NODES * D_HID];      // aggregated hidden
__device__ float g_h2[N_NODES * D_MLP];      // MLP hidden
__device__ int   g_csrc[N_EDGES];            // CSR src indices

// ---------------- CSR build ----------------
__global__ void k_zero(int* __restrict__ cnt, int* __restrict__ cur) {
    int i = blockIdx.x * blockDim.x + threadIdx.x;
    if (i < N_NODES) { cnt[i] = 0; cur[i] = 0; }
}

__global__ void k_count(const int* __restrict__ ei, int* __restrict__ cnt) {
    int e = blockIdx.x * blockDim.x + threadIdx.x;
    if (e < N_EDGES) atomicAdd(&cnt[ei[N_EDGES + e]], 1);
}

// --- hierarchical coalesced scan (scanB folded into scanC) ---
__global__ void __launch_bounds__(1024) k_scanA(
    const int* __restrict__ cnt, int* __restrict__ loc, int* __restrict__ bsum)
{
    __shared__ int sh[1024];
    int b = blockIdx.x, t = threadIdx.x;
    int idx = b * 1024 + t;
    int v = (idx < N_NODES) ? cnt[idx] : 0;
    sh[t] = v;
    __syncthreads();
    for (int off = 1; off < 1024; off <<= 1) {
        int u = (t >= off) ? sh[t - off] : 0;
        __syncthreads();
        sh[t] += u;
        __syncthreads();
    }
    if (idx < N_NODES) loc[idx] = sh[t] - v;     // exclusive
    if (t == 1023) bsum[b] = sh[1023];
}

__global__ void __launch_bounds__(1024) k_scanC(
    const int* __restrict__ cnt, const int* __restrict__ loc,
    const int* __restrict__ bsum, int* __restrict__ rowoff,
    float* __restrict__ dis)
{
    __shared__ int sb[64];
    int b = blockIdx.x, t = threadIdx.x;
    // every block scans the 49 block sums locally (cheap)
    if (t < 64) sb[t] = (t < SCAN_BLKS) ? bsum[t] : 0;
    __syncthreads();
    for (int off = 1; off < 64; off <<= 1) {
        int u = (t < 64 && t >= off) ? sb[t - off] : 0;
        __syncthreads();
        if (t < 64) sb[t] += u;
        __syncthreads();
    }
    int boff  = (b == 0) ? 0 : sb[b - 1];        // exclusive offset for this block
    int total = sb[SCAN_BLKS - 1];

    int idx = b * 1024 + t;
    if (idx < N_NODES) {
        rowoff[idx] = loc[idx] + boff;
        dis[idx] = rsqrtf((float)(cnt[idx] + 1));
    }
    if (idx == 0) rowoff[N_NODES] = total;
}

__global__ void k_fill(const int* __restrict__ ei, const int* __restrict__ rowoff,
                       int* __restrict__ cur, int* __restrict__ csrc)
{
    int e = blockIdx.x * blockDim.x + threadIdx.x;
    if (e < N_EDGES) {
        int s = ei[e];
        int d = ei[N_EDGES + e];
        int pos = rowoff[d] + atomicAdd(&cur[d], 1);
        csrc[pos] = s;
    }
}

// ---------------- FP16 tensor-core GEMM (m16n8k16, fp32 accumulate) ---------
// C[M,Ncols] = op(A[M,K]) @ B[K,Ncols] (+bias)(+relu)
// A smem: half2-packed K-contiguous; B smem: k-pair packed [k/2][n].
__device__ __forceinline__ uint32_t pack_h2(float lo, float hi) {
    __half2 h = __floats2half2_rn(lo, hi);
    return *reinterpret_cast<uint32_t*>(&h);
}

template<bool RELU_A, bool BIAS, bool RELU_OUT>
__global__ void __launch_bounds__(256, 2) k_gemm_tc(
    const float* __restrict__ A, const float* __restrict__ B,
    const float* __restrict__ bias, float* __restrict__ C,
    int M, int Ncols, int K)
{
    __shared__ uint32_t As[128][20];    // [row][k2] k2=0..15 (+pad4)
    __shared__ uint32_t Bs[16][136];    // [k2][n]  n=0..127 (+pad8)

    const int tid    = threadIdx.x;
    const int lane   = tid & 31;
    const int wid    = tid >> 5;
    const int warp_m = wid & 3;
    const int warp_n = wid >> 2;
    const int row0   = blockIdx.x * 128;
    const int col0   = blockIdx.y * 128;

    const int g  = lane >> 2;
    const int tg = lane & 3;

    float c[2][8][4];
#pragma unroll
    for (int mf = 0; mf < 2; mf++)
#pragma unroll
        for (int nf = 0; nf < 8; nf++)
#pragma unroll
            for (int i = 0; i < 4; i++) c[mf][nf][i] = 0.0f;

    const int a_r  = tid >> 3;          // 0..31 (+32*i)
    const int a_k2 = (tid & 7) * 2;     // k2 pair index (2 uint32 per float4)
    const int b_k2 = tid >> 5;          // 0..7 (+8*j)
    const int b_n4 = lane * 4;

    for (int k0 = 0; k0 < K; k0 += 32) {
        // A tile: 128 rows x 32 k  ->  half2 packed
#pragma unroll
        for (int i = 0; i < 4; i++) {
            int r = a_r + i * 32;
            float4 v = make_float4(0.f, 0.f, 0.f, 0.f);
            if (row0 + r < M)
                v = *(const float4*)(A + (size_t)(row0 + r) * K + k0 + a_k2 * 2);
            if (RELU_A) {
                v.x = fmaxf(v.x, 0.f); v.y = fmaxf(v.y, 0.f);
                v.z = fmaxf(v.z, 0.f); v.w = fmaxf(v.w, 0.f);
            }
            As[r][a_k2 + 0] = pack_h2(v.x, v.y);
            As[r][a_k2 + 1] = pack_h2(v.z, v.w);
        }
        // B tile: 32 k x 128 n -> pack k-pairs: Bs[k2][n] = (W[2k2][n], W[2k2+1][n])
#pragma unroll
        for (int j = 0; j < 2; j++) {
            int k2 = b_k2 + j * 8;
            const float* Wr0 = B + (size_t)(k0 + k2 * 2    ) * Ncols + col0 + b_n4;
            const float* Wr1 = B + (size_t)(k0 + k2 * 2 + 1) * Ncols + col0 + b_n4;
            float4 v0 = *(const float4*)Wr0;
            float4 v1 = *(const float4*)Wr1;
            uint4 p;
            p.x = pack_h2(v0.x, v1.x);
            p.y = pack_h2(v0.y, v1.y);
            p.z = pack_h2(v0.z, v1.z);
            p.w = pack_h2(v0.w, v1.w);
            *(uint4*)&Bs[k2][b_n4] = p;
        }
        __syncthreads();

#pragma unroll
        for (int kk = 0; kk < 2; kk++) {
            const int kb = kk * 8;      // k2 base
            uint32_t af[2][4];
#pragma unroll
            for (int mf = 0; mf < 2; mf++) {
                int rs = warp_m * 32 + mf * 16 + g;
                af[mf][0] = As[rs    ][kb + tg    ];
                af[mf][1] = As[rs + 8][kb + tg    ];
                af[mf][2] = As[rs    ][kb + tg + 4];
                af[mf][3] = As[rs + 8][kb + tg + 4];
            }
            uint32_t bf[8][2];
#pragma unroll
            for (int nf = 0; nf < 8; nf++) {
                int ns = warp_n * 64 + nf * 8 + g;
                bf[nf][0] = Bs[kb + tg    ][ns];
                bf[nf][1] = Bs[kb + tg + 4][ns];
            }
#pragma unroll
            for (int mf = 0; mf < 2; mf++)
#pragma unroll
                for (int nf = 0; nf < 8; nf++) {
                    asm volatile(
                        "mma.sync.aligned.m16n8k16.row.col.f32.f16.f16.f32 "
                        "{%0,%1,%2,%3}, {%4,%5,%6,%7}, {%8,%9}, {%0,%1,%2,%3};"
                        : "+f"(c[mf][nf][0]), "+f"(c[mf][nf][1]),
                          "+f"(c[mf][nf][2]), "+f"(c[mf][nf][3])
                        : "r"(af[mf][0]), "r"(af[mf][1]), "r"(af[mf][2]), "r"(af[mf][3]),
                          "r"(bf[nf][0]), "r"(bf[nf][1]));
                }
        }
        __syncthreads();
    }

#pragma unroll
    for (int mf = 0; mf < 2; mf++) {
        int rbase = row0 + warp_m * 32 + mf * 16 + g;
#pragma unroll
        for (int nf = 0; nf < 8; nf++) {
            int col = col0 + warp_n * 64 + nf * 8 + tg * 2;
            float b0 = 0.f, b1 = 0.f;
            if (BIAS) { b0 = bias[col]; b1 = bias[col + 1]; }
#pragma unroll
            for (int half = 0; half < 2; half++) {
                int r = rbase + half * 8;
                if (r < M) {
                    float v0 = c[mf][nf][half * 2 + 0] + b0;
                    float v1 = c[mf][nf][half * 2 + 1] + b1;
                    if (RELU_OUT) { v0 = fmaxf(v0, 0.f); v1 = fmaxf(v1, 0.f); }
                    float2 o = make_float2(v0, v1);
                    *(float2*)(C + (size_t)r * Ncols + col) = o;
                }
            }
        }
    }
}

// ---------------- CSR gather aggregation (R4-exact) --------------------------
__global__ void __launch_bounds__(256) k_gather(
    const int* __restrict__ csrc, const int* __restrict__ rowoff,
    const float* __restrict__ dis, const float* __restrict__ t,
    const float* __restrict__ bias, float* __restrict__ h)
{
    int w    = (blockIdx.x * 256 + threadIdx.x) >> 5;
    int lane = threadIdx.x & 31;
    if (w >= N_NODES) return;

    int beg = rowoff[w], end = rowoff[w + 1];
    float dd = dis[w];

    float4 acc = make_float4(0.f, 0.f, 0.f, 0.f);
    for (int eb = beg; eb < end; eb += 32) {
        int n = end - eb; if (n > 32) n = 32;
        int   s_l  = (lane < n) ? __ldg(csrc + eb + lane) : 0;
        float ns_l = (lane < n) ? __ldg(dis + s_l) : 0.f;
#pragma unroll 4
        for (int j = 0; j < n; j++) {
            int   s  = __shfl_sync(0xffffffffu, s_l,  j);
            float ns = __shfl_sync(0xffffffffu, ns_l, j);
            float4 v = *(const float4*)(t + (size_t)s * D_HID + lane * 4);
            acc.x = fmaf(ns, v.x, acc.x); acc.y = fmaf(ns, v.y, acc.y);
            acc.z = fmaf(ns, v.z, acc.z); acc.w = fmaf(ns, v.w, acc.w);
        }
    }

    float4 tv = *(const float4*)(t + (size_t)w * D_HID + lane * 4);
    float4 bv = ((const float4*)bias)[lane];
    float dd2 = dd * dd;
    float4 o;
    o.x = fmaf(dd, acc.x, fmaf(dd2, tv.x, bv.x));
    o.y = fmaf(dd, acc.y, fmaf(dd2, tv.y, bv.y));
    o.z = fmaf(dd, acc.z, fmaf(dd2, tv.z, bv.z));
    o.w = fmaf(dd, acc.w, fmaf(dd2, tv.w, bv.w));
    *(float4*)(h + (size_t)w * D_HID + lane * 4) = o;
}

// ---------------- final: out[M,10] = H[M,256] @ W[256,10] + b ---------------
__global__ void __launch_bounds__(256) k_final(
    const float* __restrict__ H, const float* __restrict__ W,
    const float* __restrict__ b, float* __restrict__ out, int M)
{
    __shared__ float sW[D_MLP * D_OUT];
    __shared__ float sb[D_OUT];
    for (int k = threadIdx.x; k < D_MLP * D_OUT; k += 256) sW[k] = W[k];
    if (threadIdx.x < D_OUT) sb[threadIdx.x] = b[threadIdx.x];
    __syncthreads();

    int w    = (blockIdx.x * 256 + threadIdx.x) >> 5;
    int lane = threadIdx.x & 31;
    if (w >= M) return;

    const float* hrow = H + (size_t)w * D_MLP;
    float acc[D_OUT];
#pragma unroll
    for (int j = 0; j < D_OUT; j++) acc[j] = 0.0f;

#pragma unroll
    for (int kk = 0; kk < D_MLP / 32; kk++) {
        int k = kk * 32 + lane;
        float hv = hrow[k];
        const float* wr = &sW[k * D_OUT];
#pragma unroll
        for (int j = 0; j < D_OUT; j++) acc[j] = fmaf(hv, wr[j], acc[j]);
    }
#pragma unroll
    for (int j = 0; j < D_OUT; j++) {
#pragma unroll
        for (int off = 16; off; off >>= 1)
            acc[j] += __shfl_down_sync(0xffffffffu, acc[j], off);
    }
    if (lane == 0) {
#pragma unroll
        for (int j = 0; j < D_OUT; j++)
            out[(size_t)w * D_OUT + j] = acc[j] + sb[j];
    }
}

// ---------------------------------------------------------------------------
extern "C" void kernel_launch(void* const* d_in, const int* in_sizes, int n_in,
                              void* d_out, int out_size)
{
    const float* x   = (const float*)d_in[0];
    const int*   ei  = (const int*)d_in[1];     // int32 (JAX x64 disabled)
    const float* W0  = (const float*)d_in[2];
    const float* b0  = (const float*)d_in[3];
    const float* W1  = (const float*)d_in[4];
    const float* b1  = (const float*)d_in[5];
    const float* Wm1 = (const float*)d_in[6];
    const float* bm1 = (const float*)d_in[7];
    const float* Wm2 = (const float*)d_in[8];
    const float* bm2 = (const float*)d_in[9];
    float* out = (float*)d_out;

    float *dis, *t, *h, *h2;
    int *cnt, *cur, *rowoff, *csrc, *loc, *bsum;
    cudaGetSymbolAddress((void**)&dis, g_dis);
    cudaGetSymbolAddress((void**)&t,   g_t);
    cudaGetSymbolAddress((void**)&h,   g_h);
    cudaGetSymbolAddress((void**)&h2,  g_h2);
    cudaGetSymbolAddress((void**)&cnt, g_cnt);
    cudaGetSymbolAddress((void**)&cur, g_cur);
    cudaGetSymbolAddress((void**)&rowoff, g_rowoff);
    cudaGetSymbolAddress((void**)&csrc, g_csrc);
    cudaGetSymbolAddress((void**)&loc,  g_loc);
    cudaGetSymbolAddress((void**)&bsum, g_bsum);

    // side stream + events (host objects, created once on uncaptured call)
    static cudaStream_t s_csr = nullptr;
    static cudaEvent_t  ev_fork = nullptr, ev_csr = nullptr;
    if (s_csr == nullptr) {
        cudaStreamCreateWithFlags(&s_csr, cudaStreamNonBlocking);
        cudaEventCreateWithFlags(&ev_fork, cudaEventDisableTiming);
        cudaEventCreateWithFlags(&ev_csr,  cudaEventDisableTiming);
    }

    const int ngrid = (N_NODES + 255) / 256;
    const int egrid = (N_EDGES + 255) / 256;
    const dim3 gemm_grid1((N_NODES + 127) / 128, 1);
    const dim3 gemm_grid2((N_NODES + 127) / 128, 2);
    const int  gather_grid = (N_NODES * 32 + 255) / 256;

    // ---- fork: CSR chain on side stream, GEMM-0 on main stream ----
    cudaEventRecord(ev_fork, 0);
    cudaStreamWaitEvent(s_csr, ev_fork, 0);

    k_zero <<<ngrid, 256, 0, s_csr>>>(cnt, cur);
    k_count<<<egrid, 256, 0, s_csr>>>(ei, cnt);
    k_scanA<<<SCAN_BLKS, 1024, 0, s_csr>>>(cnt, loc, bsum);
    k_scanC<<<SCAN_BLKS, 1024, 0, s_csr>>>(cnt, loc, bsum, rowoff, dis);
    k_fill <<<egrid, 256, 0, s_csr>>>(ei, rowoff, cur, csrc);
    cudaEventRecord(ev_csr, s_csr);

    k_gemm_tc<false, false, false><<<gemm_grid1, 256>>>(x, W0, nullptr, t, N_NODES, D_HID, D_IN);

    // ---- join: gather needs both CSR and t ----
    cudaStreamWaitEvent(0, ev_csr, 0);
    k_gather<<<gather_grid, 256>>>(csrc, rowoff, dis, t, b0, h);

    // layer 1 (relu fused into GEMM A-load)
    k_gemm_tc<true, false, false><<<gemm_grid1, 256>>>(h, W1, nullptr, t, N_NODES, D_HID, D_HID);
    k_gather<<<gather_grid, 256>>>(csrc, rowoff, dis, t, b1, h);

    // MLP head
    k_gemm_tc<false, true, true><<<gemm_grid2, 256>>>(h, Wm1, bm1, h2, N_NODES, D_MLP, D_HID);
    k_final<<<(N_NODES * 32 + 255) / 256, 256>>>(h2, Wm2, bm2, out, N_NODES);
}

// round 16
// speedup vs baseline: 1.7856x; 1.0251x over previous
#include <cuda_runtime.h>
#include <cuda_fp16.h>
#include <cstdint>

#define N_NODES 50000
#define N_EDGES 800000
#define D_IN    128
#define D_HID   128
#define D_MLP   256
#define D_OUT   10

#define SCAN_BLKS ((N_NODES + 1023) / 1024)   // 49

// ---------------- scratch (static device globals: no allocations) ----------
__device__ float  g_dis[N_NODES];             // deg^{-1/2}
__device__ int    g_cnt[N_NODES];             // in-degree counts
__device__ int    g_cur[N_NODES];             // fill cursors
__device__ int    g_rowoff[N_NODES + 1];      // CSR row offsets (by dst)
__device__ int    g_loc[N_NODES];             // block-local exclusive scan
__device__ int    g_bsum[SCAN_BLKS];          // per-block sums
__device__ float  g_t [N_NODES * D_HID];      // t = h @ W (fp32, gather payload)
__device__ __half g_h [N_NODES * D_HID];      // aggregated hidden (fp16: GEMM A input)
__device__ float  g_h2[N_NODES * D_MLP];      // MLP hidden (fp32)
__device__ int    g_csrc[N_EDGES];            // CSR src indices

// ---------------- CSR build ----------------
__global__ void k_zero(int* __restrict__ cnt, int* __restrict__ cur) {
    int i = blockIdx.x * blockDim.x + threadIdx.x;
    if (i < N_NODES) { cnt[i] = 0; cur[i] = 0; }
}

__global__ void k_count(const int* __restrict__ ei, int* __restrict__ cnt) {
    int e = blockIdx.x * blockDim.x + threadIdx.x;
    if (e < N_EDGES) atomicAdd(&cnt[ei[N_EDGES + e]], 1);
}

__global__ void __launch_bounds__(1024) k_scanA(
    const int* __restrict__ cnt, int* __restrict__ loc, int* __restrict__ bsum)
{
    __shared__ int sh[1024];
    int b = blockIdx.x, t = threadIdx.x;
    int idx = b * 1024 + t;
    int v = (idx < N_NODES) ? cnt[idx] : 0;
    sh[t] = v;
    __syncthreads();
    for (int off = 1; off < 1024; off <<= 1) {
        int u = (t >= off) ? sh[t - off] : 0;
        __syncthreads();
        sh[t] += u;
        __syncthreads();
    }
    if (idx < N_NODES) loc[idx] = sh[t] - v;
    if (t == 1023) bsum[b] = sh[1023];
}

__global__ void __launch_bounds__(1024) k_scanC(
    const int* __restrict__ cnt, const int* __restrict__ loc,
    const int* __restrict__ bsum, int* __restrict__ rowoff,
    float* __restrict__ dis)
{
    __shared__ int sb[64];
    int b = blockIdx.x, t = threadIdx.x;
    if (t < 64) sb[t] = (t < SCAN_BLKS) ? bsum[t] : 0;
    __syncthreads();
    for (int off = 1; off < 64; off <<= 1) {
        int u = (t < 64 && t >= off) ? sb[t - off] : 0;
        __syncthreads();
        if (t < 64) sb[t] += u;
        __syncthreads();
    }
    int boff  = (b == 0) ? 0 : sb[b - 1];
    int total = sb[SCAN_BLKS - 1];

    int idx = b * 1024 + t;
    if (idx < N_NODES) {
        rowoff[idx] = loc[idx] + boff;
        dis[idx] = rsqrtf((float)(cnt[idx] + 1));
    }
    if (idx == 0) rowoff[N_NODES] = total;
}

__global__ void k_fill(const int* __restrict__ ei, const int* __restrict__ rowoff,
                       int* __restrict__ cur, int* __restrict__ csrc)
{
    int e = blockIdx.x * blockDim.x + threadIdx.x;
    if (e < N_EDGES) {
        int s = ei[e];
        int d = ei[N_EDGES + e];
        int pos = rowoff[d] + atomicAdd(&cur[d], 1);
        csrc[pos] = s;
    }
}

// ---------------- FP16 tensor-core GEMM (m16n8k16, fp32 accumulate) ---------
// A input either fp32 (converted at load) or pre-packed fp16 half2 pairs.
__device__ __forceinline__ uint32_t pack_h2(float lo, float hi) {
    __half2 h = __floats2half2_rn(lo, hi);
    return *reinterpret_cast<uint32_t*>(&h);
}

template<bool A_HALF, bool RELU_A, bool BIAS, bool RELU_OUT>
__global__ void __launch_bounds__(256, 2) k_gemm_tc(
    const void* __restrict__ Av, const float* __restrict__ B,
    const float* __restrict__ bias, float* __restrict__ C,
    int M, int Ncols, int K)
{
    __shared__ uint32_t As[128][20];    // [row][k2]
    __shared__ uint32_t Bs[16][136];    // [k2][n]

    const int tid    = threadIdx.x;
    const int lane   = tid & 31;
    const int wid    = tid >> 5;
    const int warp_m = wid & 3;
    const int warp_n = wid >> 2;
    const int row0   = blockIdx.x * 128;
    const int col0   = blockIdx.y * 128;

    const int g  = lane >> 2;
    const int tg = lane & 3;

    float c[2][8][4];
#pragma unroll
    for (int mf = 0; mf < 2; mf++)
#pragma unroll
        for (int nf = 0; nf < 8; nf++)
#pragma unroll
            for (int i = 0; i < 4; i++) c[mf][nf][i] = 0.0f;

    const int a_r  = tid >> 3;          // 0..31 (+32*i)
    const int a_k2 = (tid & 7) * 2;     // k2 pair index (covers k = a_k2*2 .. +3)
    const int b_k2 = tid >> 5;
    const int b_n4 = lane * 4;

    const __half2 hz = __floats2half2_rn(0.f, 0.f);

    for (int k0 = 0; k0 < K; k0 += 32) {
        // ---- A tile: 128 rows x 32 k ----
#pragma unroll
        for (int i = 0; i < 4; i++) {
            int r = a_r + i * 32;
            uint32_t p0, p1;
            if (A_HALF) {
                uint2 v = make_uint2(0u, 0u);
                if (row0 + r < M)
                    v = *(const uint2*)((const __half*)Av + (size_t)(row0 + r) * K + k0 + a_k2 * 2);
                if (RELU_A) {
                    __half2 h0 = __hmax2(*reinterpret_cast<__half2*>(&v.x), hz);
                    __half2 h1 = __hmax2(*reinterpret_cast<__half2*>(&v.y), hz);
                    v.x = *reinterpret_cast<uint32_t*>(&h0);
                    v.y = *reinterpret_cast<uint32_t*>(&h1);
                }
                p0 = v.x; p1 = v.y;
            } else {
                float4 v = make_float4(0.f, 0.f, 0.f, 0.f);
                if (row0 + r < M)
                    v = *(const float4*)((const float*)Av + (size_t)(row0 + r) * K + k0 + a_k2 * 2);
                if (RELU_A) {
                    v.x = fmaxf(v.x, 0.f); v.y = fmaxf(v.y, 0.f);
                    v.z = fmaxf(v.z, 0.f); v.w = fmaxf(v.w, 0.f);
                }
                p0 = pack_h2(v.x, v.y);
                p1 = pack_h2(v.z, v.w);
            }
            As[r][a_k2 + 0] = p0;
            As[r][a_k2 + 1] = p1;
        }
        // ---- B tile: 32 k x 128 n -> k-pair packed ----
#pragma unroll
        for (int j = 0; j < 2; j++) {
            int k2 = b_k2 + j * 8;
            const float* Wr0 = B + (size_t)(k0 + k2 * 2    ) * Ncols + col0 + b_n4;
            const float* Wr1 = B + (size_t)(k0 + k2 * 2 + 1) * Ncols + col0 + b_n4;
            float4 v0 = *(const float4*)Wr0;
            float4 v1 = *(const float4*)Wr1;
            uint4 p;
            p.x = pack_h2(v0.x, v1.x);
            p.y = pack_h2(v0.y, v1.y);
            p.z = pack_h2(v0.z, v1.z);
            p.w = pack_h2(v0.w, v1.w);
            *(uint4*)&Bs[k2][b_n4] = p;
        }
        __syncthreads();

#pragma unroll
        for (int kk = 0; kk < 2; kk++) {
            const int kb = kk * 8;
            uint32_t af[2][4];
#pragma unroll
            for (int mf = 0; mf < 2; mf++) {
                int rs = warp_m * 32 + mf * 16 + g;
                af[mf][0] = As[rs    ][kb + tg    ];
                af[mf][1] = As[rs + 8][kb + tg    ];
                af[mf][2] = As[rs    ][kb + tg + 4];
                af[mf][3] = As[rs + 8][kb + tg + 4];
            }
            uint32_t bf[8][2];
#pragma unroll
            for (int nf = 0; nf < 8; nf++) {
                int ns = warp_n * 64 + nf * 8 + g;
                bf[nf][0] = Bs[kb + tg    ][ns];
                bf[nf][1] = Bs[kb + tg + 4][ns];
            }
#pragma unroll
            for (int mf = 0; mf < 2; mf++)
#pragma unroll
                for (int nf = 0; nf < 8; nf++) {
                    asm volatile(
                        "mma.sync.aligned.m16n8k16.row.col.f32.f16.f16.f32 "
                        "{%0,%1,%2,%3}, {%4,%5,%6,%7}, {%8,%9}, {%0,%1,%2,%3};"
                        : "+f"(c[mf][nf][0]), "+f"(c[mf][nf][1]),
                          "+f"(c[mf][nf][2]), "+f"(c[mf][nf][3])
                        : "r"(af[mf][0]), "r"(af[mf][1]), "r"(af[mf][2]), "r"(af[mf][3]),
                          "r"(bf[nf][0]), "r"(bf[nf][1]));
                }
        }
        __syncthreads();
    }

#pragma unroll
    for (int mf = 0; mf < 2; mf++) {
        int rbase = row0 + warp_m * 32 + mf * 16 + g;
#pragma unroll
        for (int nf = 0; nf < 8; nf++) {
            int col = col0 + warp_n * 64 + nf * 8 + tg * 2;
            float b0 = 0.f, b1 = 0.f;
            if (BIAS) { b0 = bias[col]; b1 = bias[col + 1]; }
#pragma unroll
            for (int half = 0; half < 2; half++) {
                int r = rbase + half * 8;
                if (r < M) {
                    float v0 = c[mf][nf][half * 2 + 0] + b0;
                    float v1 = c[mf][nf][half * 2 + 1] + b1;
                    if (RELU_OUT) { v0 = fmaxf(v0, 0.f); v1 = fmaxf(v1, 0.f); }
                    float2 o = make_float2(v0, v1);
                    *(float2*)(C + (size_t)r * Ncols + col) = o;
                }
            }
        }
    }
}

// ---------------- CSR gather aggregation (fp32 in, fp16 out) -----------------
__global__ void __launch_bounds__(256) k_gather(
    const int* __restrict__ csrc, const int* __restrict__ rowoff,
    const float* __restrict__ dis, const float* __restrict__ t,
    const float* __restrict__ bias, __half* __restrict__ h)
{
    int w    = (blockIdx.x * 256 + threadIdx.x) >> 5;
    int lane = threadIdx.x & 31;
    if (w >= N_NODES) return;

    int beg = rowoff[w], end = rowoff[w + 1];
    float dd = dis[w];

    float4 acc = make_float4(0.f, 0.f, 0.f, 0.f);
    for (int eb = beg; eb < end; eb += 32) {
        int n = end - eb; if (n > 32) n = 32;
        int   s_l  = (lane < n) ? __ldg(csrc + eb + lane) : 0;
        float ns_l = (lane < n) ? __ldg(dis + s_l) : 0.f;
#pragma unroll 4
        for (int j = 0; j < n; j++) {
            int   s  = __shfl_sync(0xffffffffu, s_l,  j);
            float ns = __shfl_sync(0xffffffffu, ns_l, j);
            float4 v = *(const float4*)(t + (size_t)s * D_HID + lane * 4);
            acc.x = fmaf(ns, v.x, acc.x); acc.y = fmaf(ns, v.y, acc.y);
            acc.z = fmaf(ns, v.z, acc.z); acc.w = fmaf(ns, v.w, acc.w);
        }
    }

    float4 tv = *(const float4*)(t + (size_t)w * D_HID + lane * 4);
    float4 bv = ((const float4*)bias)[lane];
    float dd2 = dd * dd;
    float ox = fmaf(dd, acc.x, fmaf(dd2, tv.x, bv.x));
    float oy = fmaf(dd, acc.y, fmaf(dd2, tv.y, bv.y));
    float oz = fmaf(dd, acc.z, fmaf(dd2, tv.z, bv.z));
    float ow = fmaf(dd, acc.w, fmaf(dd2, tv.w, bv.w));
    uint2 p;
    p.x = pack_h2(ox, oy);
    p.y = pack_h2(oz, ow);
    *(uint2*)(h + (size_t)w * D_HID + lane * 4) = p;
}

// ---------------- final: out[M,10] = H[M,256] @ W[256,10] + b ---------------
__global__ void __launch_bounds__(256) k_final(
    const float* __restrict__ H, const float* __restrict__ W,
    const float* __restrict__ b, float* __restrict__ out, int M)
{
    __shared__ float sW[D_MLP * D_OUT];
    __shared__ float sb[D_OUT];
    for (int k = threadIdx.x; k < D_MLP * D_OUT; k += 256) sW[k] = W[k];
    if (threadIdx.x < D_OUT) sb[threadIdx.x] = b[threadIdx.x];
    __syncthreads();

    int w    = (blockIdx.x * 256 + threadIdx.x) >> 5;
    int lane = threadIdx.x & 31;
    if (w >= M) return;

    const float* hrow = H + (size_t)w * D_MLP;
    float acc[D_OUT];
#pragma unroll
    for (int j = 0; j < D_OUT; j++) acc[j] = 0.0f;

#pragma unroll
    for (int kk = 0; kk < D_MLP / 32; kk++) {
        int k = kk * 32 + lane;
        float hv = hrow[k];
        const float* wr = &sW[k * D_OUT];
#pragma unroll
        for (int j = 0; j < D_OUT; j++) acc[j] = fmaf(hv, wr[j], acc[j]);
    }
#pragma unroll
    for (int j = 0; j < D_OUT; j++) {
#pragma unroll
        for (int off = 16; off; off >>= 1)
            acc[j] += __shfl_down_sync(0xffffffffu, acc[j], off);
    }
    if (lane == 0) {
#pragma unroll
        for (int j = 0; j < D_OUT; j++)
            out[(size_t)w * D_OUT + j] = acc[j] + sb[j];
    }
}

// ---------------------------------------------------------------------------
extern "C" void kernel_launch(void* const* d_in, const int* in_sizes, int n_in,
                              void* d_out, int out_size)
{
    const float* x   = (const float*)d_in[0];
    const int*   ei  = (const int*)d_in[1];     // int32 (JAX x64 disabled)
    const float* W0  = (const float*)d_in[2];
    const float* b0  = (const float*)d_in[3];
    const float* W1  = (const float*)d_in[4];
    const float* b1  = (const float*)d_in[5];
    const float* Wm1 = (const float*)d_in[6];
    const float* bm1 = (const float*)d_in[7];
    const float* Wm2 = (const float*)d_in[8];
    const float* bm2 = (const float*)d_in[9];
    float* out = (float*)d_out;

    float *dis, *t, *h2;
    __half* h;
    int *cnt, *cur, *rowoff, *csrc, *loc, *bsum;
    cudaGetSymbolAddress((void**)&dis, g_dis);
    cudaGetSymbolAddress((void**)&t,   g_t);
    cudaGetSymbolAddress((void**)&h,   g_h);
    cudaGetSymbolAddress((void**)&h2,  g_h2);
    cudaGetSymbolAddress((void**)&cnt, g_cnt);
    cudaGetSymbolAddress((void**)&cur, g_cur);
    cudaGetSymbolAddress((void**)&rowoff, g_rowoff);
    cudaGetSymbolAddress((void**)&csrc, g_csrc);
    cudaGetSymbolAddress((void**)&loc,  g_loc);
    cudaGetSymbolAddress((void**)&bsum, g_bsum);

    static cudaStream_t s_csr = nullptr;
    static cudaEvent_t  ev_fork = nullptr, ev_csr = nullptr;
    if (s_csr == nullptr) {
        cudaStreamCreateWithFlags(&s_csr, cudaStreamNonBlocking);
        cudaEventCreateWithFlags(&ev_fork, cudaEventDisableTiming);
        cudaEventCreateWithFlags(&ev_csr,  cudaEventDisableTiming);
    }

    const int ngrid = (N_NODES + 255) / 256;
    const int egrid = (N_EDGES + 255) / 256;
    const dim3 gemm_grid1((N_NODES + 127) / 128, 1);
    const dim3 gemm_grid2((N_NODES + 127) / 128, 2);
    const int  gather_grid = (N_NODES * 32 + 255) / 256;

    // ---- fork: CSR chain on side stream, GEMM-0 on main stream ----
    cudaEventRecord(ev_fork, 0);
    cudaStreamWaitEvent(s_csr, ev_fork, 0);

    k_zero <<<ngrid, 256, 0, s_csr>>>(cnt, cur);
    k_count<<<egrid, 256, 0, s_csr>>>(ei, cnt);
    k_scanA<<<SCAN_BLKS, 1024, 0, s_csr>>>(cnt, loc, bsum);
    k_scanC<<<SCAN_BLKS, 1024, 0, s_csr>>>(cnt, loc, bsum, rowoff, dis);
    k_fill <<<egrid, 256, 0, s_csr>>>(ei, rowoff, cur, csrc);
    cudaEventRecord(ev_csr, s_csr);

    // layer 0: A = x (fp32)
    k_gemm_tc<false, false, false, false><<<gemm_grid1, 256>>>(x, W0, nullptr, t, N_NODES, D_HID, D_IN);

    // ---- join ----
    cudaStreamWaitEvent(0, ev_csr, 0);
    k_gather<<<gather_grid, 256>>>(csrc, rowoff, dis, t, b0, h);

    // layer 1: A = h (fp16, relu at load)
    k_gemm_tc<true, true, false, false><<<gemm_grid1, 256>>>(h, W1, nullptr, t, N_NODES, D_HID, D_HID);
    k_gather<<<gather_grid, 256>>>(csrc, rowoff, dis, t, b1, h);

    // MLP head: A = h (fp16, no relu)
    k_gemm_tc<true, false, true, true><<<gemm_grid2, 256>>>(h, Wm1, bm1, h2, N_NODES, D_MLP, D_HID);
    k_final<<<(N_NODES * 32 + 255) / 256, 256>>>(h2, Wm2, bm2, out, N_NODES);
}

// round 17
// speedup vs baseline: 1.7987x; 1.0073x over previous
#include <cuda_runtime.h>
#include <cuda_fp16.h>
#include <cstdint>

#define N_NODES 50000
#define N_EDGES 800000
#define D_IN    128
#define D_HID   128
#define D_MLP   256
#define D_OUT   10

#define SCAN_BLKS ((N_NODES + 1023) / 1024)   // 49

// ---------------- scratch (static device globals: no allocations) ----------
__device__ float  g_dis[N_NODES];             // deg^{-1/2}
__device__ int    g_cnt[N_NODES];             // in-degree counts
__device__ int    g_cur[N_NODES];             // fill cursors
__device__ int    g_rowoff[N_NODES + 1];      // CSR row offsets (by dst)
__device__ int    g_loc[N_NODES];             // block-local exclusive scan
__device__ int    g_bsum[SCAN_BLKS];          // per-block sums
__device__ float  g_t [N_NODES * D_HID];      // t = h @ W (fp32, gather payload)
__device__ __half g_h [N_NODES * D_HID];      // aggregated hidden (fp16)
__device__ __half g_h2[N_NODES * D_MLP];      // MLP hidden (fp16)
__device__ int    g_csrc[N_EDGES];            // CSR src indices

// ---------------- CSR build ----------------
__global__ void k_zero(int* __restrict__ cnt, int* __restrict__ cur) {
    int i = blockIdx.x * blockDim.x + threadIdx.x;
    if (i < N_NODES) { cnt[i] = 0; cur[i] = 0; }
}

__global__ void k_count(const int* __restrict__ ei, int* __restrict__ cnt) {
    int e = blockIdx.x * blockDim.x + threadIdx.x;
    if (e < N_EDGES) atomicAdd(&cnt[ei[N_EDGES + e]], 1);
}

__global__ void __launch_bounds__(1024) k_scanA(
    const int* __restrict__ cnt, int* __restrict__ loc, int* __restrict__ bsum)
{
    __shared__ int sh[1024];
    int b = blockIdx.x, t = threadIdx.x;
    int idx = b * 1024 + t;
    int v = (idx < N_NODES) ? cnt[idx] : 0;
    sh[t] = v;
    __syncthreads();
    for (int off = 1; off < 1024; off <<= 1) {
        int u = (t >= off) ? sh[t - off] : 0;
        __syncthreads();
        sh[t] += u;
        __syncthreads();
    }
    if (idx < N_NODES) loc[idx] = sh[t] - v;
    if (t == 1023) bsum[b] = sh[1023];
}

__global__ void __launch_bounds__(1024) k_scanC(
    const int* __restrict__ cnt, const int* __restrict__ loc,
    const int* __restrict__ bsum, int* __restrict__ rowoff,
    float* __restrict__ dis)
{
    __shared__ int sb[64];
    int b = blockIdx.x, t = threadIdx.x;
    if (t < 64) sb[t] = (t < SCAN_BLKS) ? bsum[t] : 0;
    __syncthreads();
    for (int off = 1; off < 64; off <<= 1) {
        int u = (t < 64 && t >= off) ? sb[t - off] : 0;
        __syncthreads();
        if (t < 64) sb[t] += u;
        __syncthreads();
    }
    int boff  = (b == 0) ? 0 : sb[b - 1];
    int total = sb[SCAN_BLKS - 1];

    int idx = b * 1024 + t;
    if (idx < N_NODES) {
        rowoff[idx] = loc[idx] + boff;
        dis[idx] = rsqrtf((float)(cnt[idx] + 1));
    }
    if (idx == 0) rowoff[N_NODES] = total;
}

__global__ void k_fill(const int* __restrict__ ei, const int* __restrict__ rowoff,
                       int* __restrict__ cur, int* __restrict__ csrc)
{
    int e = blockIdx.x * blockDim.x + threadIdx.x;
    if (e < N_EDGES) {
        int s = ei[e];
        int d = ei[N_EDGES + e];
        int pos = rowoff[d] + atomicAdd(&cur[d], 1);
        csrc[pos] = s;
    }
}

// ---------------- FP16 tensor-core GEMM (m16n8k16, fp32 accumulate) ---------
__device__ __forceinline__ uint32_t pack_h2(float lo, float hi) {
    __half2 h = __floats2half2_rn(lo, hi);
    return *reinterpret_cast<uint32_t*>(&h);
}

template<bool A_HALF, bool RELU_A, bool BIAS, bool RELU_OUT, bool HALF_OUT>
__global__ void __launch_bounds__(256, 2) k_gemm_tc(
    const void* __restrict__ Av, const float* __restrict__ B,
    const float* __restrict__ bias, void* __restrict__ Cv,
    int M, int Ncols, int K)
{
    __shared__ uint32_t As[128][20];    // [row][k2]
    __shared__ uint32_t Bs[16][136];    // [k2][n]

    const int tid    = threadIdx.x;
    const int lane   = tid & 31;
    const int wid    = tid >> 5;
    const int warp_m = wid & 3;
    const int warp_n = wid >> 2;
    const int row0   = blockIdx.x * 128;
    const int col0   = blockIdx.y * 128;

    const int g  = lane >> 2;
    const int tg = lane & 3;

    float c[2][8][4];
#pragma unroll
    for (int mf = 0; mf < 2; mf++)
#pragma unroll
        for (int nf = 0; nf < 8; nf++)
#pragma unroll
            for (int i = 0; i < 4; i++) c[mf][nf][i] = 0.0f;

    const int a_r  = tid >> 3;
    const int a_k2 = (tid & 7) * 2;
    const int b_k2 = tid >> 5;
    const int b_n4 = lane * 4;

    const __half2 hz = __floats2half2_rn(0.f, 0.f);

    for (int k0 = 0; k0 < K; k0 += 32) {
#pragma unroll
        for (int i = 0; i < 4; i++) {
            int r = a_r + i * 32;
            uint32_t p0, p1;
            if (A_HALF) {
                uint2 v = make_uint2(0u, 0u);
                if (row0 + r < M)
                    v = *(const uint2*)((const __half*)Av + (size_t)(row0 + r) * K + k0 + a_k2 * 2);
                if (RELU_A) {
                    __half2 h0 = __hmax2(*reinterpret_cast<__half2*>(&v.x), hz);
                    __half2 h1 = __hmax2(*reinterpret_cast<__half2*>(&v.y), hz);
                    v.x = *reinterpret_cast<uint32_t*>(&h0);
                    v.y = *reinterpret_cast<uint32_t*>(&h1);
                }
                p0 = v.x; p1 = v.y;
            } else {
                float4 v = make_float4(0.f, 0.f, 0.f, 0.f);
                if (row0 + r < M)
                    v = *(const float4*)((const float*)Av + (size_t)(row0 + r) * K + k0 + a_k2 * 2);
                if (RELU_A) {
                    v.x = fmaxf(v.x, 0.f); v.y = fmaxf(v.y, 0.f);
                    v.z = fmaxf(v.z, 0.f); v.w = fmaxf(v.w, 0.f);
                }
                p0 = pack_h2(v.x, v.y);
                p1 = pack_h2(v.z, v.w);
            }
            As[r][a_k2 + 0] = p0;
            As[r][a_k2 + 1] = p1;
        }
#pragma unroll
        for (int j = 0; j < 2; j++) {
            int k2 = b_k2 + j * 8;
            const float* Wr0 = B + (size_t)(k0 + k2 * 2    ) * Ncols + col0 + b_n4;
            const float* Wr1 = B + (size_t)(k0 + k2 * 2 + 1) * Ncols + col0 + b_n4;
            float4 v0 = *(const float4*)Wr0;
            float4 v1 = *(const float4*)Wr1;
            uint4 p;
            p.x = pack_h2(v0.x, v1.x);
            p.y = pack_h2(v0.y, v1.y);
            p.z = pack_h2(v0.z, v1.z);
            p.w = pack_h2(v0.w, v1.w);
            *(uint4*)&Bs[k2][b_n4] = p;
        }
        __syncthreads();

#pragma unroll
        for (int kk = 0; kk < 2; kk++) {
            const int kb = kk * 8;
            uint32_t af[2][4];
#pragma unroll
            for (int mf = 0; mf < 2; mf++) {
                int rs = warp_m * 32 + mf * 16 + g;
                af[mf][0] = As[rs    ][kb + tg    ];
                af[mf][1] = As[rs + 8][kb + tg    ];
                af[mf][2] = As[rs    ][kb + tg + 4];
                af[mf][3] = As[rs + 8][kb + tg + 4];
            }
            uint32_t bf[8][2];
#pragma unroll
            for (int nf = 0; nf < 8; nf++) {
                int ns = warp_n * 64 + nf * 8 + g;
                bf[nf][0] = Bs[kb + tg    ][ns];
                bf[nf][1] = Bs[kb + tg + 4][ns];
            }
#pragma unroll
            for (int mf = 0; mf < 2; mf++)
#pragma unroll
                for (int nf = 0; nf < 8; nf++) {
                    asm volatile(
                        "mma.sync.aligned.m16n8k16.row.col.f32.f16.f16.f32 "
                        "{%0,%1,%2,%3}, {%4,%5,%6,%7}, {%8,%9}, {%0,%1,%2,%3};"
                        : "+f"(c[mf][nf][0]), "+f"(c[mf][nf][1]),
                          "+f"(c[mf][nf][2]), "+f"(c[mf][nf][3])
                        : "r"(af[mf][0]), "r"(af[mf][1]), "r"(af[mf][2]), "r"(af[mf][3]),
                          "r"(bf[nf][0]), "r"(bf[nf][1]));
                }
        }
        __syncthreads();
    }

#pragma unroll
    for (int mf = 0; mf < 2; mf++) {
        int rbase = row0 + warp_m * 32 + mf * 16 + g;
#pragma unroll
        for (int nf = 0; nf < 8; nf++) {
            int col = col0 + warp_n * 64 + nf * 8 + tg * 2;
            float b0 = 0.f, b1 = 0.f;
            if (BIAS) { b0 = bias[col]; b1 = bias[col + 1]; }
#pragma unroll
            for (int half = 0; half < 2; half++) {
                int r = rbase + half * 8;
                if (r < M) {
                    float v0 = c[mf][nf][half * 2 + 0] + b0;
                    float v1 = c[mf][nf][half * 2 + 1] + b1;
                    if (RELU_OUT) { v0 = fmaxf(v0, 0.f); v1 = fmaxf(v1, 0.f); }
                    if (HALF_OUT) {
                        uint32_t p = pack_h2(v0, v1);
                        *(uint32_t*)((__half*)Cv + (size_t)r * Ncols + col) = p;
                    } else {
                        float2 o = make_float2(v0, v1);
                        *(float2*)((float*)Cv + (size_t)r * Ncols + col) = o;
                    }
                }
            }
        }
    }
}

// ---------------- CSR gather aggregation (fp32 in, fp16 out) -----------------
__global__ void __launch_bounds__(256) k_gather(
    const int* __restrict__ csrc, const int* __restrict__ rowoff,
    const float* __restrict__ dis, const float* __restrict__ t,
    const float* __restrict__ bias, __half* __restrict__ h)
{
    int w    = (blockIdx.x * 256 + threadIdx.x) >> 5;
    int lane = threadIdx.x & 31;
    if (w >= N_NODES) return;

    int beg = rowoff[w], end = rowoff[w + 1];
    float dd = dis[w];

    float4 acc = make_float4(0.f, 0.f, 0.f, 0.f);
    for (int eb = beg; eb < end; eb += 32) {
        int n = end - eb; if (n > 32) n = 32;
        int   s_l  = (lane < n) ? __ldg(csrc + eb + lane) : 0;
        float ns_l = (lane < n) ? __ldg(dis + s_l) : 0.f;
#pragma unroll 4
        for (int j = 0; j < n; j++) {
            int   s  = __shfl_sync(0xffffffffu, s_l,  j);
            float ns = __shfl_sync(0xffffffffu, ns_l, j);
            float4 v = *(const float4*)(t + (size_t)s * D_HID + lane * 4);
            acc.x = fmaf(ns, v.x, acc.x); acc.y = fmaf(ns, v.y, acc.y);
            acc.z = fmaf(ns, v.z, acc.z); acc.w = fmaf(ns, v.w, acc.w);
        }
    }

    float4 tv = *(const float4*)(t + (size_t)w * D_HID + lane * 4);
    float4 bv = ((const float4*)bias)[lane];
    float dd2 = dd * dd;
    float ox = fmaf(dd, acc.x, fmaf(dd2, tv.x, bv.x));
    float oy = fmaf(dd, acc.y, fmaf(dd2, tv.y, bv.y));
    float oz = fmaf(dd, acc.z, fmaf(dd2, tv.z, bv.z));
    float ow = fmaf(dd, acc.w, fmaf(dd2, tv.w, bv.w));
    uint2 p;
    p.x = pack_h2(ox, oy);
    p.y = pack_h2(oz, ow);
    *(uint2*)(h + (size_t)w * D_HID + lane * 4) = p;
}

// ---------------- final: out[M,10] = H[M,256] @ W[256,10] + b  (H fp16) -----
__global__ void __launch_bounds__(256) k_final(
    const __half* __restrict__ H, const float* __restrict__ W,
    const float* __restrict__ b, float* __restrict__ out, int M)
{
    __shared__ float sW[D_MLP * D_OUT];
    __shared__ float sb[D_OUT];
    for (int k = threadIdx.x; k < D_MLP * D_OUT; k += 256) sW[k] = W[k];
    if (threadIdx.x < D_OUT) sb[threadIdx.x] = b[threadIdx.x];
    __syncthreads();

    int w    = (blockIdx.x * 256 + threadIdx.x) >> 5;
    int lane = threadIdx.x & 31;
    if (w >= M) return;

    const __half* hrow = H + (size_t)w * D_MLP;
    float acc[D_OUT];
#pragma unroll
    for (int j = 0; j < D_OUT; j++) acc[j] = 0.0f;

#pragma unroll
    for (int kk = 0; kk < D_MLP / 64; kk++) {       // 4 iterations, 2 k per lane
        int k = kk * 64 + lane * 2;
        uint32_t raw = *(const uint32_t*)(hrow + k);
        float2 hv = __half22float2(*reinterpret_cast<__half2*>(&raw));
        const float* wr0 = &sW[(k    ) * D_OUT];
        const float* wr1 = &sW[(k + 1) * D_OUT];
#pragma unroll
        for (int j = 0; j < D_OUT; j++)
            acc[j] = fmaf(hv.x, wr0[j], fmaf(hv.y, wr1[j], acc[j]));
    }
#pragma unroll
    for (int j = 0; j < D_OUT; j++) {
#pragma unroll
        for (int off = 16; off; off >>= 1)
            acc[j] += __shfl_down_sync(0xffffffffu, acc[j], off);
    }
    if (lane == 0) {
#pragma unroll
        for (int j = 0; j < D_OUT; j++)
            out[(size_t)w * D_OUT + j] = acc[j] + sb[j];
    }
}

// ---------------------------------------------------------------------------
extern "C" void kernel_launch(void* const* d_in, const int* in_sizes, int n_in,
                              void* d_out, int out_size)
{
    const float* x   = (const float*)d_in[0];
    const int*   ei  = (const int*)d_in[1];     // int32 (JAX x64 disabled)
    const float* W0  = (const float*)d_in[2];
    const float* b0  = (const float*)d_in[3];
    const float* W1  = (const float*)d_in[4];
    const float* b1  = (const float*)d_in[5];
    const float* Wm1 = (const float*)d_in[6];
    const float* bm1 = (const float*)d_in[7];
    const float* Wm2 = (const float*)d_in[8];
    const float* bm2 = (const float*)d_in[9];
    float* out = (float*)d_out;

    float *dis, *t;
    __half *h, *h2;
    int *cnt, *cur, *rowoff, *csrc, *loc, *bsum;
    cudaGetSymbolAddress((void**)&dis, g_dis);
    cudaGetSymbolAddress((void**)&t,   g_t);
    cudaGetSymbolAddress((void**)&h,   g_h);
    cudaGetSymbolAddress((void**)&h2,  g_h2);
    cudaGetSymbolAddress((void**)&cnt, g_cnt);
    cudaGetSymbolAddress((void**)&cur, g_cur);
    cudaGetSymbolAddress((void**)&rowoff, g_rowoff);
    cudaGetSymbolAddress((void**)&csrc, g_csrc);
    cudaGetSymbolAddress((void**)&loc,  g_loc);
    cudaGetSymbolAddress((void**)&bsum, g_bsum);

    static cudaStream_t s_csr = nullptr;
    static cudaEvent_t  ev_fork = nullptr, ev_csr = nullptr;
    if (s_csr == nullptr) {
        cudaStreamCreateWithFlags(&s_csr, cudaStreamNonBlocking);
        cudaEventCreateWithFlags(&ev_fork, cudaEventDisableTiming);
        cudaEventCreateWithFlags(&ev_csr,  cudaEventDisableTiming);
    }

    const int ngrid = (N_NODES + 255) / 256;
    const int egrid = (N_EDGES + 255) / 256;
    const dim3 gemm_grid1((N_NODES + 127) / 128, 1);
    const dim3 gemm_grid2((N_NODES + 127) / 128, 2);
    const int  gather_grid = (N_NODES * 32 + 255) / 256;

    // ---- fork: CSR chain on side stream, GEMM-0 on main stream ----
    cudaEventRecord(ev_fork, 0);
    cudaStreamWaitEvent(s_csr, ev_fork, 0);

    k_zero <<<ngrid, 256, 0, s_csr>>>(cnt, cur);
    k_count<<<egrid, 256, 0, s_csr>>>(ei, cnt);
    k_scanA<<<SCAN_BLKS, 1024, 0, s_csr>>>(cnt, loc, bsum);
    k_scanC<<<SCAN_BLKS, 1024, 0, s_csr>>>(cnt, loc, bsum, rowoff, dis);
    k_fill <<<egrid, 256, 0, s_csr>>>(ei, rowoff, cur, csrc);
    cudaEventRecord(ev_csr, s_csr);

    // layer 0: A = x (fp32), out = t (fp32)
    k_gemm_tc<false, false, false, false, false><<<gemm_grid1, 256>>>(
        x, W0, nullptr, t, N_NODES, D_HID, D_IN);

    // ---- join ----
    cudaStreamWaitEvent(0, ev_csr, 0);
    k_gather<<<gather_grid, 256>>>(csrc, rowoff, dis, t, b0, h);

    // layer 1: A = h (fp16, relu at load), out = t (fp32)
    k_gemm_tc<true, true, false, false, false><<<gemm_grid1, 256>>>(
        h, W1, nullptr, t, N_NODES, D_HID, D_HID);
    k_gather<<<gather_grid, 256>>>(csrc, rowoff, dis, t, b1, h);

    // MLP head: A = h (fp16), out = h2 (fp16)
    k_gemm_tc<true, false, true, true, true><<<gemm_grid2, 256>>>(
        h, Wm1, bm1, h2, N_NODES, D_MLP, D_HID);
    k_final<<<(N_NODES * 32 + 255) / 256, 256>>>(h2, Wm2, bm2, out, N_NODES);
}